// round 10
// baseline (speedup 1.0000x reference)
#include <cuda_runtime.h>
#include <math.h>
#include <stdio.h>

#define TT 512
#define BB 128
#define EE 256
#define HH 512
#define G4 2048
#define VV 512

// ---------------- static device scratch ------------------------------------
__device__ float g_X[TT * BB * EE];        // embedded input [t][b][e]
__device__ float g_pre0[TT * BB * G4];     // gate precompute buf A
__device__ float g_pre1[TT * BB * G4];     // gate precompute buf B
__device__ float g_cat[TT * BB * 2 * HH];  // enc L0 concat output [t][b][2H]
__device__ float g_hs0[TT * BB * HH];      // dec L0 output seq [t][b][H]
__device__ float g_hs1[TT * BB * HH];      // dec L1 output seq
__device__ float g_hbuf[2][2][BB * HH];    // [cell][buf][b*H+j] double-buffered h
__device__ float g_fin[2][BB * 2 * HH];    // [0]=h_enc cat, [1]=c_enc cat, [b][2H]
__device__ float g_hinit[BB * HH];         // bridge dec h init [b][j]
__device__ float g_cinit[BB * HH];         // bridge dec c init [b][j]
__device__ unsigned g_barC[1];             // monotonic arrival counter

// ---------------- small kernels --------------------------------------------
__global__ void embed_kernel(const int* __restrict__ x, const float* __restrict__ emb) {
    int p = blockIdx.x * blockDim.x + threadIdx.x;  // over T*B*(E/4)
    int e4 = p & (EE / 4 - 1);  // E/4 = 64
    int tb = p >> 6;
    int b = tb & (BB - 1);
    int t = tb >> 7;            // B = 128
    int tok = x[b * TT + t];    // x is [B, T]
    reinterpret_cast<float4*>(g_X)[(size_t)tb * (EE / 4) + e4] =
        reinterpret_cast<const float4*>(emb)[(size_t)tok * (EE / 4) + e4];
}

__global__ void zero_kernel(float* p, int n) {
    int i = blockIdx.x * blockDim.x + threadIdx.x;
    if (i < n) p[i] = 0.f;
}

__global__ void copy_kernel(float* dst, const float* src, int n) {
    int i = blockIdx.x * blockDim.x + threadIdx.x;
    if (i < n) dst[i] = src[i];
}

__global__ void initbar_kernel(unsigned* bar) { bar[0] = 0u; }

// ---------------- SGEMM: C[M,N] = A[M,K](lda) @ W[K,N] + bias[N] ------------
// remap=1: row m=(t*B+b) written to row (b*T+t) (final FC -> [B,T,V])
__global__ __launch_bounds__(256) void sgemm_kernel(
    const float* __restrict__ A, const float* __restrict__ W,
    const float* __restrict__ bias, float* __restrict__ C,
    int M, int N, int K, int lda, int remap)
{
    __shared__ float As[8][128];
    __shared__ float Ws[8][128];
    const int tid = threadIdx.x;
    const int m0 = blockIdx.y * 128, n0 = blockIdx.x * 128;
    const int ar = tid >> 1, ac = (tid & 1) * 4;
    const int wr = tid >> 5, wc = (tid & 31) * 4;
    const int tx = tid & 15, ty = tid >> 4;
    float acc[8][8];
#pragma unroll
    for (int i = 0; i < 8; i++)
#pragma unroll
        for (int j = 0; j < 8; j++) acc[i][j] = 0.f;

    const float* Aptr = A + (size_t)(m0 + ar) * lda + ac;
    const float* Wptr = W + (size_t)wr * N + n0 + wc;

    float4 av = *reinterpret_cast<const float4*>(Aptr);
    float4 wv = *reinterpret_cast<const float4*>(Wptr);
    for (int k0 = 0; k0 < K; k0 += 8) {
        __syncthreads();
        As[ac + 0][ar] = av.x; As[ac + 1][ar] = av.y;
        As[ac + 2][ar] = av.z; As[ac + 3][ar] = av.w;
        *reinterpret_cast<float4*>(&Ws[wr][wc]) = wv;
        __syncthreads();
        if (k0 + 8 < K) {
            av = *reinterpret_cast<const float4*>(Aptr + k0 + 8);
            wv = *reinterpret_cast<const float4*>(Wptr + (size_t)(k0 + 8) * N);
        }
#pragma unroll
        for (int k = 0; k < 8; k++) {
            float a[8], b[8];
            *reinterpret_cast<float4*>(a)     = *reinterpret_cast<const float4*>(&As[k][ty * 4]);
            *reinterpret_cast<float4*>(a + 4) = *reinterpret_cast<const float4*>(&As[k][ty * 4 + 64]);
            *reinterpret_cast<float4*>(b)     = *reinterpret_cast<const float4*>(&Ws[k][tx * 4]);
            *reinterpret_cast<float4*>(b + 4) = *reinterpret_cast<const float4*>(&Ws[k][tx * 4 + 64]);
#pragma unroll
            for (int i = 0; i < 8; i++)
#pragma unroll
                for (int j = 0; j < 8; j++) acc[i][j] += a[i] * b[j];
        }
    }
#pragma unroll
    for (int i = 0; i < 8; i++) {
        int row = m0 + ((i < 4) ? (ty * 4 + i) : (64 + ty * 4 + i - 4));
        int orow = remap ? ((row & (BB - 1)) * TT + (row >> 7)) : row;
#pragma unroll
        for (int jg = 0; jg < 2; jg++) {
            int col = n0 + tx * 4 + jg * 64;
            float4 v;
            v.x = acc[i][jg * 4 + 0] + bias[col + 0];
            v.y = acc[i][jg * 4 + 1] + bias[col + 1];
            v.z = acc[i][jg * 4 + 2] + bias[col + 2];
            v.w = acc[i][jg * 4 + 3] + bias[col + 3];
            *reinterpret_cast<float4*>(&C[(size_t)orow * N + col]) = v;
        }
    }
}

// ---------------- bridge ----------------------------------------------------
__global__ void bridge_kernel(const float* __restrict__ hW, const float* __restrict__ hb,
                              const float* __restrict__ cW, const float* __restrict__ cb)
{
    int p = blockIdx.x * blockDim.x + threadIdx.x;  // B*H
    int j = p & (HH - 1);
    int b = p >> 9;
    float sh = hb[j], sc = cb[j];
    const float* hrow = g_fin[0] + (size_t)b * 2 * HH;
    const float* crow = g_fin[1] + (size_t)b * 2 * HH;
    for (int k = 0; k < 2 * HH; k++) {
        sh += hrow[k] * hW[(size_t)k * HH + j];
        sc += crow[k] * cW[(size_t)k * HH + j];
    }
    g_hinit[(size_t)b * HH + j] = tanhf(sh);
    g_cinit[(size_t)b * HH + j] = tanhf(sc);
}

// ---------------- persistent LSTM recurrence --------------------------------
// grid = ncell*64 blocks x 256 threads. Block = (32 batch rows) x (32 h-cols),
// computing ALL 4 gates for its tile + pointwise update locally.
// One monotonic-counter grid barrier per step. Cross-barrier gmem h traffic via
// __ldcg/__stcg (L2-coherent) — B300 L1D is per-SM and NOT invalidated by fences.
struct RCell {
    const float* pre;     // [T][B][4H]
    const float* Wh;      // [H][4H]
    float* hs; int ldh; int colofs;     // optional output seq [t][b][ldh]
    const float* cinit;   // [b][j] or null
    float* h0; float* h1; // double-buffered h [b][j]
    float* finH; float* finC; int finOfs;  // optional finals [b][2H]
    int rev;
};

__device__ __forceinline__ float sigm_(float v) { return 1.f / (1.f + expf(-v)); }

__global__ __launch_bounds__(256) void recur_kernel(
    RCell c0, RCell c1, unsigned nb, unsigned* barC)
{
    extern __shared__ float sm[];
    float* ws  = sm;            // [64][128] Wh chunk (k, gate*32+j)   32KB
    float* hsm = sm + 8192;     // [64][36]  h chunk (k, r) padded     9.2KB
    float* ex  = sm;            // reuse ws region: [32][132] gate exchange

    const int tid = threadIdx.x;
    const RCell C = (blockIdx.x >> 6) ? c1 : c0;
    const int bid = blockIdx.x & 63;
    const int m0 = (bid >> 4) * 32;       // 4 m-groups
    const int j0 = (bid & 15) * 32;       // 16 j-groups
    const int g  = tid >> 6;              // gate 0..3
    const int jg = (tid >> 3) & 7;        // j-subgroup 0..7
    const int rg = tid & 7;               // row-subgroup 0..7
    const int r4 = rg * 4, j4 = jg * 4;
    const int pr = tid >> 3;              // pointwise owner row 0..31
    const int pj = (tid & 7) * 4;         // pointwise owner j (float4)

    float creg[4];
    if (C.cinit) {
        float4 cv = __ldcg(reinterpret_cast<const float4*>(
            &C.cinit[(size_t)(m0 + pr) * HH + j0 + pj]));
        creg[0] = cv.x; creg[1] = cv.y; creg[2] = cv.z; creg[3] = cv.w;
    } else {
        creg[0] = creg[1] = creg[2] = creg[3] = 0.f;
    }

    for (int s = 0; s < TT; s++) {
        const int t = C.rev ? (TT - 1 - s) : s;
        const float* hread = (s & 1) ? C.h1 : C.h0;
        float* hwrite      = (s & 1) ? C.h0 : C.h1;
        const float* preb = C.pre + (size_t)t * BB * G4;

        // acc init from precomputed x@Wx + b
        float acc[4][4];
#pragma unroll
        for (int ri = 0; ri < 4; ri++) {
            float4 pv = *reinterpret_cast<const float4*>(
                &preb[(size_t)(m0 + r4 + ri) * G4 + g * HH + j0 + j4]);
            acc[ri][0] = pv.x; acc[ri][1] = pv.y; acc[ri][2] = pv.z; acc[ri][3] = pv.w;
        }

        // K loop: gates += h @ Wh
        for (int k0 = 0; k0 < HH; k0 += 64) {
            __syncthreads();
            // load Wh chunk: ws[k][cc] = Wh[k0+k][ (cc>>5)*H + j0 + (cc&31) ]
            {
                const int c4 = tid & 31;          // float4 column group
                const int kb = tid >> 5;          // base k (8 rows per pass)
#pragma unroll
                for (int pass = 0; pass < 8; pass++) {
                    int k = kb + pass * 8;
                    float4 v = *reinterpret_cast<const float4*>(
                        &C.Wh[(size_t)(k0 + k) * G4 + (c4 >> 3) * HH + j0 + (c4 & 7) * 4]);
                    *reinterpret_cast<float4*>(&ws[k * 128 + c4 * 4]) = v;
                }
            }
            // load h chunk transposed via L2 (.cg): hsm[k][r] = hread[(m0+r)*H + k0+k]
            {
                const int r = tid >> 3;
                const int kq0 = tid & 7;
#pragma unroll
                for (int pass = 0; pass < 2; pass++) {
                    int kq = kq0 + pass * 8;
                    float4 hv = __ldcg(reinterpret_cast<const float4*>(
                        &hread[(size_t)(m0 + r) * HH + k0 + kq * 4]));
                    hsm[(kq * 4 + 0) * 36 + r] = hv.x;
                    hsm[(kq * 4 + 1) * 36 + r] = hv.y;
                    hsm[(kq * 4 + 2) * 36 + r] = hv.z;
                    hsm[(kq * 4 + 3) * 36 + r] = hv.w;
                }
            }
            __syncthreads();
#pragma unroll
            for (int k = 0; k < 64; k++) {
                float4 w4 = *reinterpret_cast<const float4*>(&ws[k * 128 + g * 32 + j4]);
                float4 a4 = *reinterpret_cast<const float4*>(&hsm[k * 36 + r4]);
                acc[0][0] += a4.x * w4.x; acc[0][1] += a4.x * w4.y;
                acc[0][2] += a4.x * w4.z; acc[0][3] += a4.x * w4.w;
                acc[1][0] += a4.y * w4.x; acc[1][1] += a4.y * w4.y;
                acc[1][2] += a4.y * w4.z; acc[1][3] += a4.y * w4.w;
                acc[2][0] += a4.z * w4.x; acc[2][1] += a4.z * w4.y;
                acc[2][2] += a4.z * w4.z; acc[2][3] += a4.z * w4.w;
                acc[3][0] += a4.w * w4.x; acc[3][1] += a4.w * w4.y;
                acc[3][2] += a4.w * w4.z; acc[3][3] += a4.w * w4.w;
            }
        }

        // exchange gates within block: ex[r][g*32+j]
        __syncthreads();
#pragma unroll
        for (int ri = 0; ri < 4; ri++) {
            float4 v;
            v.x = acc[ri][0]; v.y = acc[ri][1]; v.z = acc[ri][2]; v.w = acc[ri][3];
            *reinterpret_cast<float4*>(&ex[(r4 + ri) * 132 + g * 32 + j4]) = v;
        }
        __syncthreads();

        // pointwise LSTM update for owned (pr, pj..pj+3)
        {
            float4 giv = *reinterpret_cast<const float4*>(&ex[pr * 132 + 0  + pj]);
            float4 gfv = *reinterpret_cast<const float4*>(&ex[pr * 132 + 32 + pj]);
            float4 ggv = *reinterpret_cast<const float4*>(&ex[pr * 132 + 64 + pj]);
            float4 gov = *reinterpret_cast<const float4*>(&ex[pr * 132 + 96 + pj]);
            float gi[4] = {giv.x, giv.y, giv.z, giv.w};
            float gf[4] = {gfv.x, gfv.y, gfv.z, gfv.w};
            float gg[4] = {ggv.x, ggv.y, ggv.z, ggv.w};
            float go[4] = {gov.x, gov.y, gov.z, gov.w};
            float hn[4];
#pragma unroll
            for (int u = 0; u < 4; u++) {
                float cn = sigm_(gf[u]) * creg[u] + sigm_(gi[u]) * tanhf(gg[u]);
                hn[u] = sigm_(go[u]) * tanhf(cn);
                creg[u] = cn;
            }
            float4 hv; hv.x = hn[0]; hv.y = hn[1]; hv.z = hn[2]; hv.w = hn[3];
            __stcg(reinterpret_cast<float4*>(
                &hwrite[(size_t)(m0 + pr) * HH + j0 + pj]), hv);
            if (C.hs)
                *reinterpret_cast<float4*>(
                    &C.hs[(size_t)t * BB * C.ldh + (size_t)(m0 + pr) * C.ldh + C.colofs + j0 + pj]) = hv;
            if (s == TT - 1 && C.finH) {
                *reinterpret_cast<float4*>(
                    &C.finH[(size_t)(m0 + pr) * 2 * HH + C.finOfs + j0 + pj]) = hv;
                float4 cv; cv.x = creg[0]; cv.y = creg[1]; cv.z = creg[2]; cv.w = creg[3];
                *reinterpret_cast<float4*>(
                    &C.finC[(size_t)(m0 + pr) * 2 * HH + C.finOfs + j0 + pj]) = cv;
            }
        }

        // ---- grid barrier: fence -> sync -> arrive/spin -> acquire -> sync ----
        __threadfence();       // publish this thread's h writes to device scope
        __syncthreads();       // all threads' fences complete before arrival
        if (tid == 0) {
            atomicAdd(barC, 1u);
            unsigned target = (unsigned)(s + 1) * nb;
            while (*((volatile unsigned*)barC) < target) __nanosleep(64);
            __threadfence();   // acquire
        }
        __syncthreads();
    }
}

// ---------------- host ------------------------------------------------------
static void* symaddr_(const void* sym) {
    void* p = nullptr;
    cudaGetSymbolAddress(&p, sym);
    return p;
}

extern "C" void kernel_launch(void* const* d_in, const int* in_sizes, int n_in,
                              void* d_out, int out_size)
{
    // Expected element counts, dict order (V=512, E=256, H=512, B=128, T=512).
    static const int EXP[26] = {
        65536, 131072,
        524288, 1048576, 2048,  2097152, 1048576, 2048,    // enc_f L0, L1
        524288, 1048576, 2048,  2097152, 1048576, 2048,    // enc_b L0, L1
        524288, 1048576, 2048,  1048576, 1048576, 2048,    // dec L0, L1
        524288, 512, 524288, 512, 262144, 512 };
    bool ok = (n_in == 26);
    if (ok)
        for (int i = 0; i < 26; i++)
            if (in_sizes[i] != EXP[i]) { ok = false; break; }
    if (!ok) {
        fprintf(stderr, "[blstm] in_sizes mismatch, n_in=%d:", n_in);
        for (int i = 0; i < n_in && i < 32; i++) fprintf(stderr, " %d", in_sizes[i]);
        fprintf(stderr, "\n");
    }

    const int*   x       = (const int*)  d_in[0];
    const float* emb     = (const float*)d_in[1];
    const float* efWx0   = (const float*)d_in[2];
    const float* efWh0   = (const float*)d_in[3];
    const float* efb0    = (const float*)d_in[4];
    const float* efWx1   = (const float*)d_in[5];
    const float* efWh1   = (const float*)d_in[6];
    const float* efb1    = (const float*)d_in[7];
    const float* ebWx0   = (const float*)d_in[8];
    const float* ebWh0   = (const float*)d_in[9];
    const float* ebb0    = (const float*)d_in[10];
    const float* ebWx1   = (const float*)d_in[11];
    const float* ebWh1   = (const float*)d_in[12];
    const float* ebb1    = (const float*)d_in[13];
    const float* dWx0    = (const float*)d_in[14];
    const float* dWh0    = (const float*)d_in[15];
    const float* db0     = (const float*)d_in[16];
    const float* dWx1    = (const float*)d_in[17];
    const float* dWh1    = (const float*)d_in[18];
    const float* db1     = (const float*)d_in[19];
    const float* hprojW  = (const float*)d_in[20];
    const float* hprojb  = (const float*)d_in[21];
    const float* cprojW  = (const float*)d_in[22];
    const float* cprojb  = (const float*)d_in[23];
    const float* fcW     = (const float*)d_in[24];
    const float* fcb     = (const float*)d_in[25];

    float* pX    = (float*)symaddr_(g_X);
    float* pPre0 = (float*)symaddr_(g_pre0);
    float* pPre1 = (float*)symaddr_(g_pre1);
    float* pCat  = (float*)symaddr_(g_cat);
    float* pHs0  = (float*)symaddr_(g_hs0);
    float* pHs1  = (float*)symaddr_(g_hs1);
    float* pHB   = (float*)symaddr_(g_hbuf);   // [2][2][BB*HH]
    float* pFin  = (float*)symaddr_(g_fin);    // [2][BB*2H]
    float* pHin  = (float*)symaddr_(g_hinit);
    float* pCin  = (float*)symaddr_(g_cinit);
    unsigned* pBar = (unsigned*)symaddr_(g_barC);

    const int M = TT * BB;
    const int SMEMB = (8192 + 64 * 36) * 4;    // 41984 B
    cudaFuncSetAttribute(recur_kernel, cudaFuncAttributeMaxDynamicSharedMemorySize, SMEMB);

    auto hb = [&](int cell, int buf) { return pHB + ((size_t)cell * 2 + buf) * (BB * HH); };

    // 1. embedding -> g_X [t][b][e], E = 256
    embed_kernel<<<TT * BB * (EE / 4) / 256, 256>>>(x, emb);

    // 2. enc L0 precompute (K = E = 256)
    dim3 gpre(G4 / 128, M / 128);
    sgemm_kernel<<<gpre, 256>>>(pX, efWx0, efb0, pPre0, M, G4, EE, EE, 0);
    sgemm_kernel<<<gpre, 256>>>(pX, ebWx0, ebb0, pPre1, M, G4, EE, EE, 0);

    // 3. enc L0 recurrence (fwd cell 0, bwd cell 1) -> g_cat
    initbar_kernel<<<1, 1>>>(pBar);
    zero_kernel<<<(4 * BB * HH) / 256, 256>>>(pHB, 4 * BB * HH);
    {
        RCell cf{pPre0, efWh0, pCat, 2 * HH, 0,  nullptr, hb(0, 0), hb(0, 1),
                 nullptr, nullptr, 0, 0};
        RCell cb{pPre1, ebWh0, pCat, 2 * HH, HH, nullptr, hb(1, 0), hb(1, 1),
                 nullptr, nullptr, 0, 1};
        recur_kernel<<<128, 256, SMEMB>>>(cf, cb, 128u, pBar);
    }

    // 4. enc L1 precompute (K = 2H = 1024)
    sgemm_kernel<<<gpre, 256>>>(pCat, efWx1, efb1, pPre0, M, G4, 2 * HH, 2 * HH, 0);
    sgemm_kernel<<<gpre, 256>>>(pCat, ebWx1, ebb1, pPre1, M, G4, 2 * HH, 2 * HH, 0);

    // 5. enc L1 recurrence, only final states kept
    initbar_kernel<<<1, 1>>>(pBar);
    zero_kernel<<<(4 * BB * HH) / 256, 256>>>(pHB, 4 * BB * HH);
    {
        RCell ef{pPre0, efWh1, nullptr, 0, 0, nullptr, hb(0, 0), hb(0, 1),
                 pFin, pFin + (size_t)BB * 2 * HH, 0, 0};
        RCell eb{pPre1, ebWh1, nullptr, 0, 0, nullptr, hb(1, 0), hb(1, 1),
                 pFin, pFin + (size_t)BB * 2 * HH, HH, 1};
        recur_kernel<<<128, 256, SMEMB>>>(ef, eb, 128u, pBar);
    }

    // 6. bridge
    bridge_kernel<<<(BB * HH) / 256, 256>>>(hprojW, hprojb, cprojW, cprojb);

    // 7. dec L0 (input = embeddings, K = E = 256)
    sgemm_kernel<<<gpre, 256>>>(pX, dWx0, db0, pPre0, M, G4, EE, EE, 0);
    initbar_kernel<<<1, 1>>>(pBar);
    copy_kernel<<<(BB * HH) / 256, 256>>>(hb(0, 0), pHin, BB * HH);
    {
        RCell d0{pPre0, dWh0, pHs0, HH, 0, pCin, hb(0, 0), hb(0, 1),
                 nullptr, nullptr, 0, 0};
        recur_kernel<<<64, 256, SMEMB>>>(d0, d0, 64u, pBar);
    }

    // 8. dec L1 (input = dec L0 output, K = H = 512)
    sgemm_kernel<<<gpre, 256>>>(pHs0, dWx1, db1, pPre1, M, G4, HH, HH, 0);
    initbar_kernel<<<1, 1>>>(pBar);
    copy_kernel<<<(BB * HH) / 256, 256>>>(hb(0, 0), pHin, BB * HH);
    {
        RCell d1{pPre1, dWh1, pHs1, HH, 0, pCin, hb(0, 0), hb(0, 1),
                 nullptr, nullptr, 0, 0};
        recur_kernel<<<64, 256, SMEMB>>>(d1, d1, 64u, pBar);
    }

    // 9. final FC with [t][b] -> [b][t] remap
    dim3 gfc(VV / 128, M / 128);
    sgemm_kernel<<<gfc, 256>>>(pHs1, fcW, fcb, (float*)d_out, M, VV, HH, HH, 1);
}

// round 11
// speedup vs baseline: 1.1039x; 1.1039x over previous
#include <cuda_runtime.h>
#include <math.h>
#include <stdio.h>

#define TT 512
#define BB 128
#define EE 256
#define HH 512
#define G4 2048
#define VV 512

// ---------------- static device scratch ------------------------------------
__device__ float g_X[TT * BB * EE];
__device__ float g_pre0[TT * BB * G4];
__device__ float g_pre1[TT * BB * G4];
__device__ float g_cat[TT * BB * 2 * HH];
__device__ float g_hs0[TT * BB * HH];
__device__ float g_hs1[TT * BB * HH];
__device__ float g_hbuf[2][2][BB * HH];
__device__ float g_fin[2][BB * 2 * HH];
__device__ float g_hinit[BB * HH];
__device__ float g_cinit[BB * HH];
__device__ unsigned g_barC[1];

// ---------------- small kernels --------------------------------------------
__global__ void embed_kernel(const int* __restrict__ x, const float* __restrict__ emb) {
    int p = blockIdx.x * blockDim.x + threadIdx.x;  // over T*B*(E/4)
    int e4 = p & (EE / 4 - 1);  // E/4 = 64
    int tb = p >> 6;
    int b = tb & (BB - 1);
    int t = tb >> 7;
    int tok = x[b * TT + t];
    reinterpret_cast<float4*>(g_X)[(size_t)tb * (EE / 4) + e4] =
        reinterpret_cast<const float4*>(emb)[(size_t)tok * (EE / 4) + e4];
}

__global__ void zero_kernel(float* p, int n) {
    int i = blockIdx.x * blockDim.x + threadIdx.x;
    if (i < n) p[i] = 0.f;
}

__global__ void copy_kernel(float* dst, const float* src, int n) {
    int i = blockIdx.x * blockDim.x + threadIdx.x;
    if (i < n) dst[i] = src[i];
}

__global__ void initbar_kernel(unsigned* bar) { bar[0] = 0u; }

// ---------------- tf32 helpers ----------------------------------------------
__device__ __forceinline__ unsigned f2tf(float f) {
    unsigned r;
    asm("cvt.rna.tf32.f32 %0, %1;" : "=r"(r) : "f"(f));
    return r;
}

__device__ __forceinline__ void mma_tf32(float* c, unsigned a0, unsigned a1,
                                         unsigned a2, unsigned a3,
                                         unsigned b0, unsigned b1) {
    asm volatile(
        "mma.sync.aligned.m16n8k8.row.col.f32.tf32.tf32.f32 "
        "{%0,%1,%2,%3}, {%4,%5,%6,%7}, {%8,%9}, {%0,%1,%2,%3};"
        : "+f"(c[0]), "+f"(c[1]), "+f"(c[2]), "+f"(c[3])
        : "r"(a0), "r"(a1), "r"(a2), "r"(a3), "r"(b0), "r"(b1));
}

// ---------------- tf32 tensor-core GEMM: C = A[M,K] @ W[K,N] + bias ----------
// 128x128 tile, K-chunk 32. 8 warps: 2(m) x 4(n), warp tile 64x32.
// remap=1: row m=(t*B+b) written to row (b*T+t).
__global__ __launch_bounds__(256) void tgemm_kernel(
    const float* __restrict__ A, const float* __restrict__ W,
    const float* __restrict__ bias, float* __restrict__ C,
    int M, int N, int K, int lda, int remap)
{
    __shared__ unsigned As[32][132];   // [k][m], tf32 bit patterns
    __shared__ unsigned Ws[32][132];   // [k][n]
    const int tid = threadIdx.x;
    const int m0 = blockIdx.y * 128, n0 = blockIdx.x * 128;
    const int warp = tid >> 5, lane = tid & 31;
    const int wm = (warp & 1) * 64;
    const int wn = (warp >> 1) * 32;
    const int gid = lane >> 2, tig = lane & 3;

    float acc[4][4][4];
#pragma unroll
    for (int mt = 0; mt < 4; mt++)
#pragma unroll
        for (int nt = 0; nt < 4; nt++)
#pragma unroll
            for (int u = 0; u < 4; u++) acc[mt][nt][u] = 0.f;

    for (int k0 = 0; k0 < K; k0 += 32) {
        __syncthreads();
        // A chunk: 128m x 32k -> As[k][m] (transposed), tf32-converted
#pragma unroll
        for (int it = 0; it < 4; it++) {
            int slot = tid + it * 256;      // 0..1023
            int m = slot & 127;
            int kc = slot >> 7;             // 0..7
            float4 v = *reinterpret_cast<const float4*>(
                &A[(size_t)(m0 + m) * lda + k0 + kc * 4]);
            As[kc * 4 + 0][m] = f2tf(v.x);
            As[kc * 4 + 1][m] = f2tf(v.y);
            As[kc * 4 + 2][m] = f2tf(v.z);
            As[kc * 4 + 3][m] = f2tf(v.w);
        }
        // W chunk: 32k x 128n -> Ws[k][n]
#pragma unroll
        for (int it = 0; it < 4; it++) {
            int slot = tid + it * 256;      // 0..1023 float4 slots
            int k = slot >> 5;              // 0..31
            int nc = slot & 31;
            float4 v = *reinterpret_cast<const float4*>(
                &W[(size_t)(k0 + k) * N + n0 + nc * 4]);
            Ws[k][nc * 4 + 0] = f2tf(v.x);
            Ws[k][nc * 4 + 1] = f2tf(v.y);
            Ws[k][nc * 4 + 2] = f2tf(v.z);
            Ws[k][nc * 4 + 3] = f2tf(v.w);
        }
        __syncthreads();
#pragma unroll
        for (int kk = 0; kk < 4; kk++) {
            unsigned bf[4][2];
#pragma unroll
            for (int nt = 0; nt < 4; nt++) {
                bf[nt][0] = Ws[kk * 8 + tig][wn + nt * 8 + gid];
                bf[nt][1] = Ws[kk * 8 + 4 + tig][wn + nt * 8 + gid];
            }
#pragma unroll
            for (int mt = 0; mt < 4; mt++) {
                unsigned a0 = As[kk * 8 + tig][wm + mt * 16 + gid];
                unsigned a1 = As[kk * 8 + tig][wm + mt * 16 + 8 + gid];
                unsigned a2 = As[kk * 8 + 4 + tig][wm + mt * 16 + gid];
                unsigned a3 = As[kk * 8 + 4 + tig][wm + mt * 16 + 8 + gid];
#pragma unroll
                for (int nt = 0; nt < 4; nt++)
                    mma_tf32(acc[mt][nt], a0, a1, a2, a3, bf[nt][0], bf[nt][1]);
            }
        }
    }
    // epilogue: bias + (optional remap) store, float2 per (mt,nt,half)
#pragma unroll
    for (int nt = 0; nt < 4; nt++) {
        int col = n0 + wn + nt * 8 + 2 * tig;
        float b0v = bias[col], b1v = bias[col + 1];
#pragma unroll
        for (int mt = 0; mt < 4; mt++) {
            int row0 = m0 + wm + mt * 16 + gid;
            int row1 = row0 + 8;
            int o0 = remap ? ((row0 & (BB - 1)) * TT + (row0 >> 7)) : row0;
            int o1 = remap ? ((row1 & (BB - 1)) * TT + (row1 >> 7)) : row1;
            float2 v0, v1;
            v0.x = acc[mt][nt][0] + b0v; v0.y = acc[mt][nt][1] + b1v;
            v1.x = acc[mt][nt][2] + b0v; v1.y = acc[mt][nt][3] + b1v;
            *reinterpret_cast<float2*>(&C[(size_t)o0 * N + col]) = v0;
            *reinterpret_cast<float2*>(&C[(size_t)o1 * N + col]) = v1;
        }
    }
}

// ---------------- bridge ----------------------------------------------------
__global__ void bridge_kernel(const float* __restrict__ hW, const float* __restrict__ hb,
                              const float* __restrict__ cW, const float* __restrict__ cb)
{
    int p = blockIdx.x * blockDim.x + threadIdx.x;
    int j = p & (HH - 1);
    int b = p >> 9;
    float sh = hb[j], sc = cb[j];
    const float* hrow = g_fin[0] + (size_t)b * 2 * HH;
    const float* crow = g_fin[1] + (size_t)b * 2 * HH;
    for (int k = 0; k < 2 * HH; k++) {
        sh += hrow[k] * hW[(size_t)k * HH + j];
        sc += crow[k] * cW[(size_t)k * HH + j];
    }
    g_hinit[(size_t)b * HH + j] = tanhf(sh);
    g_cinit[(size_t)b * HH + j] = tanhf(sc);
}

// ---------------- persistent LSTM recurrence (unchanged from R10) ------------
struct RCell {
    const float* pre;
    const float* Wh;
    float* hs; int ldh; int colofs;
    const float* cinit;
    float* h0; float* h1;
    float* finH; float* finC; int finOfs;
    int rev;
};

__device__ __forceinline__ float sigm_(float v) { return 1.f / (1.f + expf(-v)); }

__global__ __launch_bounds__(256) void recur_kernel(
    RCell c0, RCell c1, unsigned nb, unsigned* barC)
{
    extern __shared__ float sm[];
    float* ws  = sm;            // [64][128]
    float* hsm = sm + 8192;     // [64][36]
    float* ex  = sm;            // reuse: [32][132]

    const int tid = threadIdx.x;
    const RCell C = (blockIdx.x >> 6) ? c1 : c0;
    const int bid = blockIdx.x & 63;
    const int m0 = (bid >> 4) * 32;
    const int j0 = (bid & 15) * 32;
    const int g  = tid >> 6;
    const int jg = (tid >> 3) & 7;
    const int rg = tid & 7;
    const int r4 = rg * 4, j4 = jg * 4;
    const int pr = tid >> 3;
    const int pj = (tid & 7) * 4;

    float creg[4];
    if (C.cinit) {
        float4 cv = __ldcg(reinterpret_cast<const float4*>(
            &C.cinit[(size_t)(m0 + pr) * HH + j0 + pj]));
        creg[0] = cv.x; creg[1] = cv.y; creg[2] = cv.z; creg[3] = cv.w;
    } else {
        creg[0] = creg[1] = creg[2] = creg[3] = 0.f;
    }

    for (int s = 0; s < TT; s++) {
        const int t = C.rev ? (TT - 1 - s) : s;
        const float* hread = (s & 1) ? C.h1 : C.h0;
        float* hwrite      = (s & 1) ? C.h0 : C.h1;
        const float* preb = C.pre + (size_t)t * BB * G4;

        float acc[4][4];
#pragma unroll
        for (int ri = 0; ri < 4; ri++) {
            float4 pv = *reinterpret_cast<const float4*>(
                &preb[(size_t)(m0 + r4 + ri) * G4 + g * HH + j0 + j4]);
            acc[ri][0] = pv.x; acc[ri][1] = pv.y; acc[ri][2] = pv.z; acc[ri][3] = pv.w;
        }

        for (int k0 = 0; k0 < HH; k0 += 64) {
            __syncthreads();
            {
                const int c4 = tid & 31;
                const int kb = tid >> 5;
#pragma unroll
                for (int pass = 0; pass < 8; pass++) {
                    int k = kb + pass * 8;
                    float4 v = *reinterpret_cast<const float4*>(
                        &C.Wh[(size_t)(k0 + k) * G4 + (c4 >> 3) * HH + j0 + (c4 & 7) * 4]);
                    *reinterpret_cast<float4*>(&ws[k * 128 + c4 * 4]) = v;
                }
            }
            {
                const int r = tid >> 3;
                const int kq0 = tid & 7;
#pragma unroll
                for (int pass = 0; pass < 2; pass++) {
                    int kq = kq0 + pass * 8;
                    float4 hv = __ldcg(reinterpret_cast<const float4*>(
                        &hread[(size_t)(m0 + r) * HH + k0 + kq * 4]));
                    hsm[(kq * 4 + 0) * 36 + r] = hv.x;
                    hsm[(kq * 4 + 1) * 36 + r] = hv.y;
                    hsm[(kq * 4 + 2) * 36 + r] = hv.z;
                    hsm[(kq * 4 + 3) * 36 + r] = hv.w;
                }
            }
            __syncthreads();
#pragma unroll
            for (int k = 0; k < 64; k++) {
                float4 w4 = *reinterpret_cast<const float4*>(&ws[k * 128 + g * 32 + j4]);
                float4 a4 = *reinterpret_cast<const float4*>(&hsm[k * 36 + r4]);
                acc[0][0] += a4.x * w4.x; acc[0][1] += a4.x * w4.y;
                acc[0][2] += a4.x * w4.z; acc[0][3] += a4.x * w4.w;
                acc[1][0] += a4.y * w4.x; acc[1][1] += a4.y * w4.y;
                acc[1][2] += a4.y * w4.z; acc[1][3] += a4.y * w4.w;
                acc[2][0] += a4.z * w4.x; acc[2][1] += a4.z * w4.y;
                acc[2][2] += a4.z * w4.z; acc[2][3] += a4.z * w4.w;
                acc[3][0] += a4.w * w4.x; acc[3][1] += a4.w * w4.y;
                acc[3][2] += a4.w * w4.z; acc[3][3] += a4.w * w4.w;
            }
        }

        __syncthreads();
#pragma unroll
        for (int ri = 0; ri < 4; ri++) {
            float4 v;
            v.x = acc[ri][0]; v.y = acc[ri][1]; v.z = acc[ri][2]; v.w = acc[ri][3];
            *reinterpret_cast<float4*>(&ex[(r4 + ri) * 132 + g * 32 + j4]) = v;
        }
        __syncthreads();

        {
            float4 giv = *reinterpret_cast<const float4*>(&ex[pr * 132 + 0  + pj]);
            float4 gfv = *reinterpret_cast<const float4*>(&ex[pr * 132 + 32 + pj]);
            float4 ggv = *reinterpret_cast<const float4*>(&ex[pr * 132 + 64 + pj]);
            float4 gov = *reinterpret_cast<const float4*>(&ex[pr * 132 + 96 + pj]);
            float gi[4] = {giv.x, giv.y, giv.z, giv.w};
            float gf[4] = {gfv.x, gfv.y, gfv.z, gfv.w};
            float gg[4] = {ggv.x, ggv.y, ggv.z, ggv.w};
            float go[4] = {gov.x, gov.y, gov.z, gov.w};
            float hn[4];
#pragma unroll
            for (int u = 0; u < 4; u++) {
                float cn = sigm_(gf[u]) * creg[u] + sigm_(gi[u]) * tanhf(gg[u]);
                hn[u] = sigm_(go[u]) * tanhf(cn);
                creg[u] = cn;
            }
            float4 hv; hv.x = hn[0]; hv.y = hn[1]; hv.z = hn[2]; hv.w = hn[3];
            __stcg(reinterpret_cast<float4*>(
                &hwrite[(size_t)(m0 + pr) * HH + j0 + pj]), hv);
            if (C.hs)
                *reinterpret_cast<float4*>(
                    &C.hs[(size_t)t * BB * C.ldh + (size_t)(m0 + pr) * C.ldh + C.colofs + j0 + pj]) = hv;
            if (s == TT - 1 && C.finH) {
                *reinterpret_cast<float4*>(
                    &C.finH[(size_t)(m0 + pr) * 2 * HH + C.finOfs + j0 + pj]) = hv;
                float4 cv; cv.x = creg[0]; cv.y = creg[1]; cv.z = creg[2]; cv.w = creg[3];
                *reinterpret_cast<float4*>(
                    &C.finC[(size_t)(m0 + pr) * 2 * HH + C.finOfs + j0 + pj]) = cv;
            }
        }

        __threadfence();
        __syncthreads();
        if (tid == 0) {
            atomicAdd(barC, 1u);
            unsigned target = (unsigned)(s + 1) * nb;
            while (*((volatile unsigned*)barC) < target) __nanosleep(64);
            __threadfence();
        }
        __syncthreads();
    }
}

// ---------------- host ------------------------------------------------------
static void* symaddr_(const void* sym) {
    void* p = nullptr;
    cudaGetSymbolAddress(&p, sym);
    return p;
}

extern "C" void kernel_launch(void* const* d_in, const int* in_sizes, int n_in,
                              void* d_out, int out_size)
{
    const int*   x       = (const int*)  d_in[0];
    const float* emb     = (const float*)d_in[1];
    const float* efWx0   = (const float*)d_in[2];
    const float* efWh0   = (const float*)d_in[3];
    const float* efb0    = (const float*)d_in[4];
    const float* efWx1   = (const float*)d_in[5];
    const float* efWh1   = (const float*)d_in[6];
    const float* efb1    = (const float*)d_in[7];
    const float* ebWx0   = (const float*)d_in[8];
    const float* ebWh0   = (const float*)d_in[9];
    const float* ebb0    = (const float*)d_in[10];
    const float* ebWx1   = (const float*)d_in[11];
    const float* ebWh1   = (const float*)d_in[12];
    const float* ebb1    = (const float*)d_in[13];
    const float* dWx0    = (const float*)d_in[14];
    const float* dWh0    = (const float*)d_in[15];
    const float* db0     = (const float*)d_in[16];
    const float* dWx1    = (const float*)d_in[17];
    const float* dWh1    = (const float*)d_in[18];
    const float* db1     = (const float*)d_in[19];
    const float* hprojW  = (const float*)d_in[20];
    const float* hprojb  = (const float*)d_in[21];
    const float* cprojW  = (const float*)d_in[22];
    const float* cprojb  = (const float*)d_in[23];
    const float* fcW     = (const float*)d_in[24];
    const float* fcb     = (const float*)d_in[25];

    float* pX    = (float*)symaddr_(g_X);
    float* pPre0 = (float*)symaddr_(g_pre0);
    float* pPre1 = (float*)symaddr_(g_pre1);
    float* pCat  = (float*)symaddr_(g_cat);
    float* pHs0  = (float*)symaddr_(g_hs0);
    float* pHs1  = (float*)symaddr_(g_hs1);
    float* pHB   = (float*)symaddr_(g_hbuf);
    float* pFin  = (float*)symaddr_(g_fin);
    float* pHin  = (float*)symaddr_(g_hinit);
    float* pCin  = (float*)symaddr_(g_cinit);
    unsigned* pBar = (unsigned*)symaddr_(g_barC);

    const int M = TT * BB;
    const int SMEMB = (8192 + 64 * 36) * 4;
    cudaFuncSetAttribute(recur_kernel, cudaFuncAttributeMaxDynamicSharedMemorySize, SMEMB);

    auto hb = [&](int cell, int buf) { return pHB + ((size_t)cell * 2 + buf) * (BB * HH); };

    // 1. embedding
    embed_kernel<<<TT * BB * (EE / 4) / 256, 256>>>(x, emb);

    // 2. enc L0 precompute (K = 256), tf32 tensor cores
    dim3 gpre(G4 / 128, M / 128);
    tgemm_kernel<<<gpre, 256>>>(pX, efWx0, efb0, pPre0, M, G4, EE, EE, 0);
    tgemm_kernel<<<gpre, 256>>>(pX, ebWx0, ebb0, pPre1, M, G4, EE, EE, 0);

    // 3. enc L0 recurrence
    initbar_kernel<<<1, 1>>>(pBar);
    zero_kernel<<<(4 * BB * HH) / 256, 256>>>(pHB, 4 * BB * HH);
    {
        RCell cf{pPre0, efWh0, pCat, 2 * HH, 0,  nullptr, hb(0, 0), hb(0, 1),
                 nullptr, nullptr, 0, 0};
        RCell cb{pPre1, ebWh0, pCat, 2 * HH, HH, nullptr, hb(1, 0), hb(1, 1),
                 nullptr, nullptr, 0, 1};
        recur_kernel<<<128, 256, SMEMB>>>(cf, cb, 128u, pBar);
    }

    // 4. enc L1 precompute (K = 1024)
    tgemm_kernel<<<gpre, 256>>>(pCat, efWx1, efb1, pPre0, M, G4, 2 * HH, 2 * HH, 0);
    tgemm_kernel<<<gpre, 256>>>(pCat, ebWx1, ebb1, pPre1, M, G4, 2 * HH, 2 * HH, 0);

    // 5. enc L1 recurrence (final states only)
    initbar_kernel<<<1, 1>>>(pBar);
    zero_kernel<<<(4 * BB * HH) / 256, 256>>>(pHB, 4 * BB * HH);
    {
        RCell ef{pPre0, efWh1, nullptr, 0, 0, nullptr, hb(0, 0), hb(0, 1),
                 pFin, pFin + (size_t)BB * 2 * HH, 0, 0};
        RCell eb{pPre1, ebWh1, nullptr, 0, 0, nullptr, hb(1, 0), hb(1, 1),
                 pFin, pFin + (size_t)BB * 2 * HH, HH, 1};
        recur_kernel<<<128, 256, SMEMB>>>(ef, eb, 128u, pBar);
    }

    // 6. bridge
    bridge_kernel<<<(BB * HH) / 256, 256>>>(hprojW, hprojb, cprojW, cprojb);

    // 7. dec L0 (K = 256)
    tgemm_kernel<<<gpre, 256>>>(pX, dWx0, db0, pPre0, M, G4, EE, EE, 0);
    initbar_kernel<<<1, 1>>>(pBar);
    copy_kernel<<<(BB * HH) / 256, 256>>>(hb(0, 0), pHin, BB * HH);
    {
        RCell d0{pPre0, dWh0, pHs0, HH, 0, pCin, hb(0, 0), hb(0, 1),
                 nullptr, nullptr, 0, 0};
        recur_kernel<<<64, 256, SMEMB>>>(d0, d0, 64u, pBar);
    }

    // 8. dec L1 (K = 512)
    tgemm_kernel<<<gpre, 256>>>(pHs0, dWx1, db1, pPre1, M, G4, HH, HH, 0);
    initbar_kernel<<<1, 1>>>(pBar);
    copy_kernel<<<(BB * HH) / 256, 256>>>(hb(0, 0), pHin, BB * HH);
    {
        RCell d1{pPre1, dWh1, pHs1, HH, 0, pCin, hb(0, 0), hb(0, 1),
                 nullptr, nullptr, 0, 0};
        recur_kernel<<<64, 256, SMEMB>>>(d1, d1, 64u, pBar);
    }

    // 9. final FC with remap
    dim3 gfc(VV / 128, M / 128);
    tgemm_kernel<<<gfc, 256>>>(pHs1, fcW, fcb, (float*)d_out, M, VV, HH, HH, 1);
}

// round 12
// speedup vs baseline: 2.1998x; 1.9927x over previous
#include <cuda_runtime.h>
#include <cuda_bf16.h>
#include <math.h>

#define TT 512
#define BB 128
#define EE 256
#define HH 512
#define G4 2048
#define VV 512

// ---------------- static device scratch ------------------------------------
__device__ float g_X[TT * BB * EE];
__device__ float g_pre0[TT * BB * G4];
__device__ float g_pre1[TT * BB * G4];
__device__ float g_cat[TT * BB * 2 * HH];
__device__ float g_hs0[TT * BB * HH];
__device__ float g_hs1[TT * BB * HH];
__device__ float g_fin[2][BB * 2 * HH];
__device__ float g_hinit[BB * HH];
__device__ float g_cinit[BB * HH];
__device__ unsigned g_barC[1];
// split-bf16 weights: [6 weights][hi/lo][bn 32][kp 256][c 64] packed 2-bf16/uint
__device__ unsigned g_wsp[6][2][32 * 256 * 64];
// split-bf16 h double buffers: [cell 2][buf 2][hi/lo 2][kp 256][m 128]
__device__ unsigned g_hsp[2][2][2][256 * 128];

// ---------------- small kernels --------------------------------------------
__global__ void embed_kernel(const int* __restrict__ x, const float* __restrict__ emb) {
    int p = blockIdx.x * blockDim.x + threadIdx.x;
    int e4 = p & (EE / 4 - 1);
    int tb = p >> 6;
    int b = tb & (BB - 1);
    int t = tb >> 7;
    int tok = x[b * TT + t];
    reinterpret_cast<float4*>(g_X)[(size_t)tb * (EE / 4) + e4] =
        reinterpret_cast<const float4*>(emb)[(size_t)tok * (EE / 4) + e4];
}

__global__ void zero_kernel(float* p, int n) {
    int i = blockIdx.x * blockDim.x + threadIdx.x;
    if (i < n) p[i] = 0.f;
}

__global__ void initbar_kernel(unsigned* bar) { bar[0] = 0u; }

// ---------------- bf16 split helpers ----------------------------------------
__device__ __forceinline__ unsigned pack_bf16x2(float lo, float hi) {
    unsigned r;
    asm("cvt.rn.bf16x2.f32 %0, %1, %2;" : "=r"(r) : "f"(hi), "f"(lo));
    return r;
}

// Split W[512][2048] into hi/lo bf16, packed along k, sliced per block:
// out[bn*16384 + kp*64 + c], c = g*16+jj maps to col g*512 + bn*16 + jj.
__global__ void wconv_kernel(const float* __restrict__ W,
                             unsigned* __restrict__ hi, unsigned* __restrict__ lo) {
    int p = blockIdx.x * blockDim.x + threadIdx.x;   // 524288
    int bn = p >> 14;
    int rem = p & 16383;
    int kp = rem >> 6;
    int c = rem & 63;
    int G = (c >> 4) * HH + bn * 16 + (c & 15);
    float w0 = W[(size_t)(2 * kp) * G4 + G];
    float w1 = W[(size_t)(2 * kp + 1) * G4 + G];
    __nv_bfloat16 b0 = __float2bfloat16_rn(w0);
    __nv_bfloat16 b1 = __float2bfloat16_rn(w1);
    hi[p] = (unsigned)__bfloat16_as_ushort(b0) |
            ((unsigned)__bfloat16_as_ushort(b1) << 16);
    lo[p] = pack_bf16x2(w0 - __bfloat162float(b0), w1 - __bfloat162float(b1));
}

// Split h[b][j] fp32 into packed [kp][m] hi/lo (decoder init).
__global__ void hsplit_kernel(const float* __restrict__ h,
                              unsigned* __restrict__ hi, unsigned* __restrict__ lo) {
    int p = blockIdx.x * blockDim.x + threadIdx.x;   // 32768
    int kp = p >> 7, m = p & 127;
    float v0 = h[(size_t)m * HH + 2 * kp];
    float v1 = h[(size_t)m * HH + 2 * kp + 1];
    __nv_bfloat16 b0 = __float2bfloat16_rn(v0);
    __nv_bfloat16 b1 = __float2bfloat16_rn(v1);
    hi[p] = (unsigned)__bfloat16_as_ushort(b0) |
            ((unsigned)__bfloat16_as_ushort(b1) << 16);
    lo[p] = pack_bf16x2(v0 - __bfloat162float(b0), v1 - __bfloat162float(b1));
}

// ---------------- tf32 helpers (pre-GEMMs, unchanged from R11) ---------------
__device__ __forceinline__ unsigned f2tf(float f) {
    unsigned r;
    asm("cvt.rna.tf32.f32 %0, %1;" : "=r"(r) : "f"(f));
    return r;
}

__device__ __forceinline__ void mma_tf32(float* c, unsigned a0, unsigned a1,
                                         unsigned a2, unsigned a3,
                                         unsigned b0, unsigned b1) {
    asm volatile(
        "mma.sync.aligned.m16n8k8.row.col.f32.tf32.tf32.f32 "
        "{%0,%1,%2,%3}, {%4,%5,%6,%7}, {%8,%9}, {%0,%1,%2,%3};"
        : "+f"(c[0]), "+f"(c[1]), "+f"(c[2]), "+f"(c[3])
        : "r"(a0), "r"(a1), "r"(a2), "r"(a3), "r"(b0), "r"(b1));
}

__global__ __launch_bounds__(256) void tgemm_kernel(
    const float* __restrict__ A, const float* __restrict__ W,
    const float* __restrict__ bias, float* __restrict__ C,
    int M, int N, int K, int lda, int remap)
{
    __shared__ unsigned As[32][132];
    __shared__ unsigned Ws[32][132];
    const int tid = threadIdx.x;
    const int m0 = blockIdx.y * 128, n0 = blockIdx.x * 128;
    const int warp = tid >> 5, lane = tid & 31;
    const int wm = (warp & 1) * 64;
    const int wn = (warp >> 1) * 32;
    const int gid = lane >> 2, tig = lane & 3;

    float acc[4][4][4];
#pragma unroll
    for (int mt = 0; mt < 4; mt++)
#pragma unroll
        for (int nt = 0; nt < 4; nt++)
#pragma unroll
            for (int u = 0; u < 4; u++) acc[mt][nt][u] = 0.f;

    for (int k0 = 0; k0 < K; k0 += 32) {
        __syncthreads();
#pragma unroll
        for (int it = 0; it < 4; it++) {
            int slot = tid + it * 256;
            int m = slot & 127;
            int kc = slot >> 7;
            float4 v = *reinterpret_cast<const float4*>(
                &A[(size_t)(m0 + m) * lda + k0 + kc * 4]);
            As[kc * 4 + 0][m] = f2tf(v.x);
            As[kc * 4 + 1][m] = f2tf(v.y);
            As[kc * 4 + 2][m] = f2tf(v.z);
            As[kc * 4 + 3][m] = f2tf(v.w);
        }
#pragma unroll
        for (int it = 0; it < 4; it++) {
            int slot = tid + it * 256;
            int k = slot >> 5;
            int nc = slot & 31;
            float4 v = *reinterpret_cast<const float4*>(
                &W[(size_t)(k0 + k) * N + n0 + nc * 4]);
            Ws[k][nc * 4 + 0] = f2tf(v.x);
            Ws[k][nc * 4 + 1] = f2tf(v.y);
            Ws[k][nc * 4 + 2] = f2tf(v.z);
            Ws[k][nc * 4 + 3] = f2tf(v.w);
        }
        __syncthreads();
#pragma unroll
        for (int kk = 0; kk < 4; kk++) {
            unsigned bf[4][2];
#pragma unroll
            for (int nt = 0; nt < 4; nt++) {
                bf[nt][0] = Ws[kk * 8 + tig][wn + nt * 8 + gid];
                bf[nt][1] = Ws[kk * 8 + 4 + tig][wn + nt * 8 + gid];
            }
#pragma unroll
            for (int mt = 0; mt < 4; mt++) {
                unsigned a0 = As[kk * 8 + tig][wm + mt * 16 + gid];
                unsigned a1 = As[kk * 8 + tig][wm + mt * 16 + 8 + gid];
                unsigned a2 = As[kk * 8 + 4 + tig][wm + mt * 16 + gid];
                unsigned a3 = As[kk * 8 + 4 + tig][wm + mt * 16 + 8 + gid];
#pragma unroll
                for (int nt = 0; nt < 4; nt++)
                    mma_tf32(acc[mt][nt], a0, a1, a2, a3, bf[nt][0], bf[nt][1]);
            }
        }
    }
#pragma unroll
    for (int nt = 0; nt < 4; nt++) {
        int col = n0 + wn + nt * 8 + 2 * tig;
        float b0v = bias[col], b1v = bias[col + 1];
#pragma unroll
        for (int mt = 0; mt < 4; mt++) {
            int row0 = m0 + wm + mt * 16 + gid;
            int row1 = row0 + 8;
            int o0 = remap ? ((row0 & (BB - 1)) * TT + (row0 >> 7)) : row0;
            int o1 = remap ? ((row1 & (BB - 1)) * TT + (row1 >> 7)) : row1;
            float2 v0, v1;
            v0.x = acc[mt][nt][0] + b0v; v0.y = acc[mt][nt][1] + b1v;
            v1.x = acc[mt][nt][2] + b0v; v1.y = acc[mt][nt][3] + b1v;
            *reinterpret_cast<float2*>(&C[(size_t)o0 * N + col]) = v0;
            *reinterpret_cast<float2*>(&C[(size_t)o1 * N + col]) = v1;
        }
    }
}

// ---------------- bridge ----------------------------------------------------
__global__ void bridge_kernel(const float* __restrict__ hW, const float* __restrict__ hb,
                              const float* __restrict__ cW, const float* __restrict__ cb)
{
    int p = blockIdx.x * blockDim.x + threadIdx.x;
    int j = p & (HH - 1);
    int b = p >> 9;
    float sh = hb[j], sc = cb[j];
    const float* hrow = g_fin[0] + (size_t)b * 2 * HH;
    const float* crow = g_fin[1] + (size_t)b * 2 * HH;
    for (int k = 0; k < 2 * HH; k++) {
        sh += hrow[k] * hW[(size_t)k * HH + j];
        sc += crow[k] * cW[(size_t)k * HH + j];
    }
    g_hinit[(size_t)b * HH + j] = tanhf(sh);
    g_cinit[(size_t)b * HH + j] = tanhf(sc);
}

// ---------------- bf16 MMA recurrence ----------------------------------------
__device__ __forceinline__ void mma_bf16(float* c, const unsigned* a,
                                         unsigned b0, unsigned b1) {
    asm volatile(
        "mma.sync.aligned.m16n8k16.row.col.f32.bf16.bf16.f32 "
        "{%0,%1,%2,%3}, {%4,%5,%6,%7}, {%8,%9}, {%0,%1,%2,%3};"
        : "+f"(c[0]), "+f"(c[1]), "+f"(c[2]), "+f"(c[3])
        : "r"(a[0]), "r"(a[1]), "r"(a[2]), "r"(a[3]), "r"(b0), "r"(b1));
}

__device__ __forceinline__ float sigm_(float v) { return 1.f / (1.f + expf(-v)); }

struct RCell2 {
    const float* pre;                 // [T][B][4H]
    const unsigned* whi; const unsigned* wlo;   // split W, per-cell [bn][256][64]
    float* hs; int ldh; int colofs;   // optional output seq
    const float* cinit;               // [b][j] fp32 or null
    unsigned* h0hi; unsigned* h0lo;   // split h double buffers [kp 256][m 128]
    unsigned* h1hi; unsigned* h1lo;
    float* finH; float* finC; int finOfs;
    int rev;
};

// Block tile: MT rows x 64 gate cols (4 gates x 16 j). nbpc blocks per cell.
// Warp grid 2(m) x 4(n); warp tile m(MT/2) x n16. W split resident in smem.
// smem stride 72 words (conflict-free fragment loads).
template <int MT>
__global__ __launch_bounds__(256) void recur2_kernel(
    RCell2 c0, RCell2 c1, int nbpc, unsigned nb, unsigned* barC)
{
    extern __shared__ unsigned smu[];
    unsigned* Wphi = smu;             // 256*72
    unsigned* Wplo = smu + 18432;
    unsigned* Aphi = smu + 36864;     // 64*72
    unsigned* Aplo = smu + 41472;
    float* ex = (float*)(smu + 46080);  // 64*72 floats

    const int tid = threadIdx.x;
    const bool c1sel = (blockIdx.x >= nbpc);
    const RCell2 C = c1sel ? c1 : c0;
    const int bic = c1sel ? (blockIdx.x - nbpc) : blockIdx.x;
    const int bn = bic & 31;
    const int m0 = (bic >> 5) * MT;
    const int j0 = bn * 16;
    const int warp = tid >> 5, lane = tid & 31;
    const int gid = lane >> 2, tig = lane & 3;
    const int wm = warp & 1, wn = warp >> 1;
    constexpr int WTM = MT / 32;

    // load resident split W slice (256 kp x 64 c)
    {
        const uint4* srch = reinterpret_cast<const uint4*>(C.whi + (size_t)bn * 16384);
        const uint4* srcl = reinterpret_cast<const uint4*>(C.wlo + (size_t)bn * 16384);
#pragma unroll
        for (int i = 0; i < 16; i++) {
            int f4 = tid + i * 256;
            int row = f4 >> 4, q = f4 & 15;
            *reinterpret_cast<uint4*>(&Wphi[row * 72 + q * 4]) = srch[f4];
            *reinterpret_cast<uint4*>(&Wplo[row * 72 + q * 4]) = srcl[f4];
        }
    }

    // pointwise ownership: thread -> (m, j-quad)
    const int pm = tid & (MT - 1);
    const int pjq = tid / MT;
    const bool pact = pjq < 4;
    float creg[4] = {0.f, 0.f, 0.f, 0.f};
    if (pact && C.cinit) {
        float4 cv = __ldcg(reinterpret_cast<const float4*>(
            &C.cinit[(size_t)(m0 + pm) * HH + j0 + pjq * 4]));
        creg[0] = cv.x; creg[1] = cv.y; creg[2] = cv.z; creg[3] = cv.w;
    }
    __syncthreads();

    for (int s = 0; s < TT; s++) {
        const int t = C.rev ? (TT - 1 - s) : s;
        const unsigned* rhi = (s & 1) ? C.h1hi : C.h0hi;
        const unsigned* rlo = (s & 1) ? C.h1lo : C.h0lo;
        unsigned* whi_ = (s & 1) ? C.h0hi : C.h1hi;
        unsigned* wlo_ = (s & 1) ? C.h0lo : C.h1lo;
        const float* preb = C.pre + (size_t)t * BB * G4;

        float4 pg[4];
        if (pact) {
#pragma unroll
            for (int g = 0; g < 4; g++)
                pg[g] = __ldg(reinterpret_cast<const float4*>(
                    &preb[(size_t)(m0 + pm) * G4 + g * HH + j0 + pjq * 4]));
        }

        float acc[WTM][2][4];
#pragma unroll
        for (int mt = 0; mt < WTM; mt++)
#pragma unroll
            for (int nt = 0; nt < 2; nt++)
#pragma unroll
                for (int u = 0; u < 4; u++) acc[mt][nt][u] = 0.f;

        for (int ch = 0; ch < 4; ch++) {
            __syncthreads();
            // stage split h chunk: 64 kp x MT m
            {
                constexpr int F4 = 64 * MT / 4;
                constexpr int PT = F4 / 256;
                const int kpb = ch * 64;
#pragma unroll
                for (int i = 0; i < PT; i++) {
                    int f4 = tid + i * 256;
                    int row = f4 / (MT / 4), q = f4 % (MT / 4);
                    *reinterpret_cast<uint4*>(&Aphi[row * 72 + q * 4]) =
                        __ldcg(reinterpret_cast<const uint4*>(
                            &rhi[(size_t)(kpb + row) * 128 + m0 + q * 4]));
                    *reinterpret_cast<uint4*>(&Aplo[row * 72 + q * 4]) =
                        __ldcg(reinterpret_cast<const uint4*>(
                            &rlo[(size_t)(kpb + row) * 128 + m0 + q * 4]));
                }
            }
            __syncthreads();
#pragma unroll
            for (int kc = 0; kc < 8; kc++) {
                const int r0 = (kc * 8 + tig) * 72;
                const int r1 = r0 + 4 * 72;
                unsigned ah[WTM][4], al[WTM][4];
#pragma unroll
                for (int mt = 0; mt < WTM; mt++) {
                    const int am = wm * (MT / 2) + mt * 16 + gid;
                    ah[mt][0] = Aphi[r0 + am]; ah[mt][1] = Aphi[r0 + am + 8];
                    ah[mt][2] = Aphi[r1 + am]; ah[mt][3] = Aphi[r1 + am + 8];
                    al[mt][0] = Aplo[r0 + am]; al[mt][1] = Aplo[r0 + am + 8];
                    al[mt][2] = Aplo[r1 + am]; al[mt][3] = Aplo[r1 + am + 8];
                }
                const int wr0 = (ch * 64 + kc * 8 + tig) * 72;
                const int wr1 = wr0 + 4 * 72;
#pragma unroll
                for (int nt = 0; nt < 2; nt++) {
                    const int nn = wn * 16 + nt * 8 + gid;
                    unsigned bh0 = Wphi[wr0 + nn], bh1 = Wphi[wr1 + nn];
                    unsigned bl0 = Wplo[wr0 + nn], bl1 = Wplo[wr1 + nn];
#pragma unroll
                    for (int mt = 0; mt < WTM; mt++) {
                        mma_bf16(acc[mt][nt], ah[mt], bh0, bh1);
                        mma_bf16(acc[mt][nt], ah[mt], bl0, bl1);
                        mma_bf16(acc[mt][nt], al[mt], bh0, bh1);
                    }
                }
            }
        }

        // exchange gates via smem
#pragma unroll
        for (int mt = 0; mt < WTM; mt++)
#pragma unroll
            for (int nt = 0; nt < 2; nt++) {
                int mr = (wm * (MT / 2) + mt * 16 + gid) * 72;
                int col = wn * 16 + nt * 8 + 2 * tig;
                float2 v0, v1;
                v0.x = acc[mt][nt][0]; v0.y = acc[mt][nt][1];
                v1.x = acc[mt][nt][2]; v1.y = acc[mt][nt][3];
                *reinterpret_cast<float2*>(&ex[mr + col]) = v0;
                *reinterpret_cast<float2*>(&ex[mr + 8 * 72 + col]) = v1;
            }
        __syncthreads();

        if (pact) {
            float4 gi = *reinterpret_cast<const float4*>(&ex[pm * 72 + 0  + pjq * 4]);
            float4 gf = *reinterpret_cast<const float4*>(&ex[pm * 72 + 16 + pjq * 4]);
            float4 gg = *reinterpret_cast<const float4*>(&ex[pm * 72 + 32 + pjq * 4]);
            float4 go = *reinterpret_cast<const float4*>(&ex[pm * 72 + 48 + pjq * 4]);
            float I[4] = {gi.x + pg[0].x, gi.y + pg[0].y, gi.z + pg[0].z, gi.w + pg[0].w};
            float F[4] = {gf.x + pg[1].x, gf.y + pg[1].y, gf.z + pg[1].z, gf.w + pg[1].w};
            float Gg[4] = {gg.x + pg[2].x, gg.y + pg[2].y, gg.z + pg[2].z, gg.w + pg[2].w};
            float O[4] = {go.x + pg[3].x, go.y + pg[3].y, go.z + pg[3].z, go.w + pg[3].w};
            float hn[4];
#pragma unroll
            for (int u = 0; u < 4; u++) {
                float cn = sigm_(F[u]) * creg[u] + sigm_(I[u]) * tanhf(Gg[u]);
                hn[u] = sigm_(O[u]) * tanhf(cn);
                creg[u] = cn;
            }
            // write split h (packed along j-pairs)
            __nv_bfloat16 b0 = __float2bfloat16_rn(hn[0]);
            __nv_bfloat16 b1 = __float2bfloat16_rn(hn[1]);
            __nv_bfloat16 b2 = __float2bfloat16_rn(hn[2]);
            __nv_bfloat16 b3 = __float2bfloat16_rn(hn[3]);
            unsigned hp0 = (unsigned)__bfloat16_as_ushort(b0) |
                           ((unsigned)__bfloat16_as_ushort(b1) << 16);
            unsigned hp1 = (unsigned)__bfloat16_as_ushort(b2) |
                           ((unsigned)__bfloat16_as_ushort(b3) << 16);
            unsigned lp0 = pack_bf16x2(hn[0] - __bfloat162float(b0),
                                       hn[1] - __bfloat162float(b1));
            unsigned lp1 = pack_bf16x2(hn[2] - __bfloat162float(b2),
                                       hn[3] - __bfloat162float(b3));
            int kp0 = (j0 + pjq * 4) >> 1;
            __stcg(&whi_[(size_t)kp0 * 128 + m0 + pm], hp0);
            __stcg(&whi_[(size_t)(kp0 + 1) * 128 + m0 + pm], hp1);
            __stcg(&wlo_[(size_t)kp0 * 128 + m0 + pm], lp0);
            __stcg(&wlo_[(size_t)(kp0 + 1) * 128 + m0 + pm], lp1);
            if (C.hs) {
                float4 hv; hv.x = hn[0]; hv.y = hn[1]; hv.z = hn[2]; hv.w = hn[3];
                *reinterpret_cast<float4*>(
                    &C.hs[(size_t)t * BB * C.ldh + (size_t)(m0 + pm) * C.ldh +
                          C.colofs + j0 + pjq * 4]) = hv;
            }
            if (s == TT - 1 && C.finH) {
                float4 hv; hv.x = hn[0]; hv.y = hn[1]; hv.z = hn[2]; hv.w = hn[3];
                float4 cv; cv.x = creg[0]; cv.y = creg[1]; cv.z = creg[2]; cv.w = creg[3];
                *reinterpret_cast<float4*>(
                    &C.finH[(size_t)(m0 + pm) * 2 * HH + C.finOfs + j0 + pjq * 4]) = hv;
                *reinterpret_cast<float4*>(
                    &C.finC[(size_t)(m0 + pm) * 2 * HH + C.finOfs + j0 + pjq * 4]) = cv;
            }
        }

        // grid barrier
        __threadfence();
        __syncthreads();
        if (tid == 0) {
            atomicAdd(barC, 1u);
            unsigned target = (unsigned)(s + 1) * nb;
            while (*((volatile unsigned*)barC) < target) __nanosleep(64);
            __threadfence();
        }
        __syncthreads();
    }
}

// ---------------- host ------------------------------------------------------
static void* symaddr_(const void* sym) {
    void* p = nullptr;
    cudaGetSymbolAddress(&p, sym);
    return p;
}

extern "C" void kernel_launch(void* const* d_in, const int* in_sizes, int n_in,
                              void* d_out, int out_size)
{
    const int*   x       = (const int*)  d_in[0];
    const float* emb     = (const float*)d_in[1];
    const float* efWx0   = (const float*)d_in[2];
    const float* efWh0   = (const float*)d_in[3];
    const float* efb0    = (const float*)d_in[4];
    const float* efWx1   = (const float*)d_in[5];
    const float* efWh1   = (const float*)d_in[6];
    const float* efb1    = (const float*)d_in[7];
    const float* ebWx0   = (const float*)d_in[8];
    const float* ebWh0   = (const float*)d_in[9];
    const float* ebb0    = (const float*)d_in[10];
    const float* ebWx1   = (const float*)d_in[11];
    const float* ebWh1   = (const float*)d_in[12];
    const float* ebb1    = (const float*)d_in[13];
    const float* dWx0    = (const float*)d_in[14];
    const float* dWh0    = (const float*)d_in[15];
    const float* db0     = (const float*)d_in[16];
    const float* dWx1    = (const float*)d_in[17];
    const float* dWh1    = (const float*)d_in[18];
    const float* db1     = (const float*)d_in[19];
    const float* hprojW  = (const float*)d_in[20];
    const float* hprojb  = (const float*)d_in[21];
    const float* cprojW  = (const float*)d_in[22];
    const float* cprojb  = (const float*)d_in[23];
    const float* fcW     = (const float*)d_in[24];
    const float* fcb     = (const float*)d_in[25];

    float* pX    = (float*)symaddr_(g_X);
    float* pPre0 = (float*)symaddr_(g_pre0);
    float* pPre1 = (float*)symaddr_(g_pre1);
    float* pCat  = (float*)symaddr_(g_cat);
    float* pHs0  = (float*)symaddr_(g_hs0);
    float* pHs1  = (float*)symaddr_(g_hs1);
    float* pFin  = (float*)symaddr_(g_fin);
    float* pHin  = (float*)symaddr_(g_hinit);
    float* pCin  = (float*)symaddr_(g_cinit);
    unsigned* pBar = (unsigned*)symaddr_(g_barC);
    unsigned* pWsp = (unsigned*)symaddr_(g_wsp);
    unsigned* pHsp = (unsigned*)symaddr_(g_hsp);

    const int M = TT * BB;
    const int SME2 = 50688 * 4;   // 202752 B
    cudaFuncSetAttribute(recur2_kernel<64>, cudaFuncAttributeMaxDynamicSharedMemorySize, SME2);
    cudaFuncSetAttribute(recur2_kernel<32>, cudaFuncAttributeMaxDynamicSharedMemorySize, SME2);

    const size_t WSZ = 32 * 256 * 64;   // uints per weight per hi/lo
    auto wsp = [&](int w, int hl) { return pWsp + ((size_t)w * 2 + hl) * WSZ; };
    auto hsp = [&](int cell, int buf, int hl) {
        return pHsp + (((size_t)cell * 2 + buf) * 2 + hl) * 32768;
    };

    // 0. split weights
    wconv_kernel<<<2048, 256>>>(efWh0, wsp(0, 0), wsp(0, 1));
    wconv_kernel<<<2048, 256>>>(ebWh0, wsp(1, 0), wsp(1, 1));
    wconv_kernel<<<2048, 256>>>(efWh1, wsp(2, 0), wsp(2, 1));
    wconv_kernel<<<2048, 256>>>(ebWh1, wsp(3, 0), wsp(3, 1));
    wconv_kernel<<<2048, 256>>>(dWh0,  wsp(4, 0), wsp(4, 1));
    wconv_kernel<<<2048, 256>>>(dWh1,  wsp(5, 0), wsp(5, 1));

    // 1. embedding
    embed_kernel<<<TT * BB * (EE / 4) / 256, 256>>>(x, emb);

    // 2. enc L0 precompute (K=256)
    dim3 gpre(G4 / 128, M / 128);
    tgemm_kernel<<<gpre, 256>>>(pX, efWx0, efb0, pPre0, M, G4, EE, EE, 0);
    tgemm_kernel<<<gpre, 256>>>(pX, ebWx0, ebb0, pPre1, M, G4, EE, EE, 0);

    // 3. enc L0 recurrence
    initbar_kernel<<<1, 1>>>(pBar);
    zero_kernel<<<1024, 256>>>((float*)pHsp, 262144);
    {
        RCell2 cf{pPre0, wsp(0, 0), wsp(0, 1), pCat, 2 * HH, 0, nullptr,
                  hsp(0, 0, 0), hsp(0, 0, 1), hsp(0, 1, 0), hsp(0, 1, 1),
                  nullptr, nullptr, 0, 0};
        RCell2 cb{pPre1, wsp(1, 0), wsp(1, 1), pCat, 2 * HH, HH, nullptr,
                  hsp(1, 0, 0), hsp(1, 0, 1), hsp(1, 1, 0), hsp(1, 1, 1),
                  nullptr, nullptr, 0, 1};
        recur2_kernel<64><<<128, 256, SME2>>>(cf, cb, 64, 128u, pBar);
    }

    // 4. enc L1 precompute (K=1024)
    tgemm_kernel<<<gpre, 256>>>(pCat, efWx1, efb1, pPre0, M, G4, 2 * HH, 2 * HH, 0);
    tgemm_kernel<<<gpre, 256>>>(pCat, ebWx1, ebb1, pPre1, M, G4, 2 * HH, 2 * HH, 0);

    // 5. enc L1 recurrence (finals only)
    initbar_kernel<<<1, 1>>>(pBar);
    zero_kernel<<<1024, 256>>>((float*)pHsp, 262144);
    {
        RCell2 ef{pPre0, wsp(2, 0), wsp(2, 1), nullptr, 0, 0, nullptr,
                  hsp(0, 0, 0), hsp(0, 0, 1), hsp(0, 1, 0), hsp(0, 1, 1),
                  pFin, pFin + (size_t)BB * 2 * HH, 0, 0};
        RCell2 eb{pPre1, wsp(3, 0), wsp(3, 1), nullptr, 0, 0, nullptr,
                  hsp(1, 0, 0), hsp(1, 0, 1), hsp(1, 1, 0), hsp(1, 1, 1),
                  pFin, pFin + (size_t)BB * 2 * HH, HH, 1};
        recur2_kernel<64><<<128, 256, SME2>>>(ef, eb, 64, 128u, pBar);
    }

    // 6. bridge
    bridge_kernel<<<(BB * HH) / 256, 256>>>(hprojW, hprojb, cprojW, cprojb);

    // 7. dec L0 (K=256)
    tgemm_kernel<<<gpre, 256>>>(pX, dWx0, db0, pPre0, M, G4, EE, EE, 0);
    initbar_kernel<<<1, 1>>>(pBar);
    hsplit_kernel<<<128, 256>>>(pHin, hsp(0, 0, 0), hsp(0, 0, 1));
    {
        RCell2 d0{pPre0, wsp(4, 0), wsp(4, 1), pHs0, HH, 0, pCin,
                  hsp(0, 0, 0), hsp(0, 0, 1), hsp(0, 1, 0), hsp(0, 1, 1),
                  nullptr, nullptr, 0, 0};
        recur2_kernel<32><<<128, 256, SME2>>>(d0, d0, 128, 128u, pBar);
    }

    // 8. dec L1 (K=512)
    tgemm_kernel<<<gpre, 256>>>(pHs0, dWx1, db1, pPre1, M, G4, HH, HH, 0);
    initbar_kernel<<<1, 1>>>(pBar);
    hsplit_kernel<<<128, 256>>>(pHin, hsp(0, 0, 0), hsp(0, 0, 1));
    {
        RCell2 d1{pPre1, wsp(5, 0), wsp(5, 1), pHs1, HH, 0, pCin,
                  hsp(0, 0, 0), hsp(0, 0, 1), hsp(0, 1, 0), hsp(0, 1, 1),
                  nullptr, nullptr, 0, 0};
        recur2_kernel<32><<<128, 256, SME2>>>(d1, d1, 128, 128u, pBar);
    }

    // 9. final FC with remap
    dim3 gfc(VV / 128, M / 128);
    tgemm_kernel<<<gfc, 256>>>(pHs1, fcW, fcb, (float*)d_out, M, VV, HH, HH, 1);
}

// round 13
// speedup vs baseline: 2.5100x; 1.1410x over previous
#include <cuda_runtime.h>
#include <cuda_bf16.h>
#include <math.h>

#define TT 512
#define BB 128
#define EE 256
#define HH 512
#define G4 2048
#define VV 512

// ---------------- static device scratch ------------------------------------
__device__ float g_X[TT * BB * EE];
__device__ float g_pre0[TT * BB * G4];
__device__ float g_pre1[TT * BB * G4];
__device__ float g_cat[TT * BB * 2 * HH];
__device__ float g_hs0[TT * BB * HH];
__device__ float g_hs1[TT * BB * HH];
__device__ float g_fin[2][BB * 2 * HH];
__device__ float g_hinit[BB * HH];
__device__ float g_cinit[BB * HH];
__device__ unsigned g_barC[1];
// split-bf16 recurrent weights: [6][hi/lo][bn 32][kp 256][c 64]
__device__ unsigned g_wsp[6][2][32 * 256 * 64];
// split-bf16 h double buffers: [cell 2][buf 2][hi/lo 2][kp 256][m 128]
__device__ unsigned g_hsp[2][2][2][256 * 128];
// tf32-rounded input weights: 7 matrices (max 2H*G4 = 2097152 floats)
__device__ float g_wx[7][2097152];

// ---------------- tf32 rounding helpers -------------------------------------
__device__ __forceinline__ unsigned f2tf(float f) {
    unsigned r;
    asm("cvt.rna.tf32.f32 %0, %1;" : "=r"(r) : "f"(f));
    return r;
}
__device__ __forceinline__ float tfr(float f) { return __uint_as_float(f2tf(f)); }

__global__ void tfround_kernel(const float* __restrict__ in, float* __restrict__ out, int n) {
    int i = blockIdx.x * blockDim.x + threadIdx.x;
    if (i < n) out[i] = tfr(in[i]);
}

// ---------------- small kernels --------------------------------------------
__global__ void embed_kernel(const int* __restrict__ x, const float* __restrict__ emb) {
    int p = blockIdx.x * blockDim.x + threadIdx.x;
    int e4 = p & (EE / 4 - 1);
    int tb = p >> 6;
    int b = tb & (BB - 1);
    int t = tb >> 7;
    int tok = x[b * TT + t];
    float4 v = reinterpret_cast<const float4*>(emb)[(size_t)tok * (EE / 4) + e4];
    v.x = tfr(v.x); v.y = tfr(v.y); v.z = tfr(v.z); v.w = tfr(v.w);
    reinterpret_cast<float4*>(g_X)[(size_t)tb * (EE / 4) + e4] = v;
}

__global__ void zero_kernel(float* p, int n) {
    int i = blockIdx.x * blockDim.x + threadIdx.x;
    if (i < n) p[i] = 0.f;
}

__global__ void initbar_kernel(unsigned* bar) { bar[0] = 0u; }

// ---------------- bf16 split helpers ----------------------------------------
__device__ __forceinline__ unsigned pack_bf16x2(float lo, float hi) {
    unsigned r;
    asm("cvt.rn.bf16x2.f32 %0, %1, %2;" : "=r"(r) : "f"(hi), "f"(lo));
    return r;
}

__global__ void wconv_kernel(const float* __restrict__ W,
                             unsigned* __restrict__ hi, unsigned* __restrict__ lo) {
    int p = blockIdx.x * blockDim.x + threadIdx.x;   // 524288
    int bn = p >> 14;
    int rem = p & 16383;
    int kp = rem >> 6;
    int c = rem & 63;
    int G = (c >> 4) * HH + bn * 16 + (c & 15);
    float w0 = W[(size_t)(2 * kp) * G4 + G];
    float w1 = W[(size_t)(2 * kp + 1) * G4 + G];
    __nv_bfloat16 b0 = __float2bfloat16_rn(w0);
    __nv_bfloat16 b1 = __float2bfloat16_rn(w1);
    hi[p] = (unsigned)__bfloat16_as_ushort(b0) |
            ((unsigned)__bfloat16_as_ushort(b1) << 16);
    lo[p] = pack_bf16x2(w0 - __bfloat162float(b0), w1 - __bfloat162float(b1));
}

__global__ void hsplit_kernel(const float* __restrict__ h,
                              unsigned* __restrict__ hi, unsigned* __restrict__ lo) {
    int p = blockIdx.x * blockDim.x + threadIdx.x;   // 32768
    int kp = p >> 7, m = p & 127;
    float v0 = h[(size_t)m * HH + 2 * kp];
    float v1 = h[(size_t)m * HH + 2 * kp + 1];
    __nv_bfloat16 b0 = __float2bfloat16_rn(v0);
    __nv_bfloat16 b1 = __float2bfloat16_rn(v1);
    hi[p] = (unsigned)__bfloat16_as_ushort(b0) |
            ((unsigned)__bfloat16_as_ushort(b1) << 16);
    lo[p] = pack_bf16x2(v0 - __bfloat162float(b0), v1 - __bfloat162float(b1));
}

// ---------------- cp.async helpers ------------------------------------------
__device__ __forceinline__ void cpasync16(void* smem, const void* gmem) {
    unsigned saddr = (unsigned)__cvta_generic_to_shared(smem);
    asm volatile("cp.async.cg.shared.global [%0], [%1], 16;\n" :: "r"(saddr), "l"(gmem));
}

__device__ __forceinline__ void mma_tf32(float* c, unsigned a0, unsigned a1,
                                         unsigned a2, unsigned a3,
                                         unsigned b0, unsigned b1) {
    asm volatile(
        "mma.sync.aligned.m16n8k8.row.col.f32.tf32.tf32.f32 "
        "{%0,%1,%2,%3}, {%4,%5,%6,%7}, {%8,%9}, {%0,%1,%2,%3};"
        : "+f"(c[0]), "+f"(c[1]), "+f"(c[2]), "+f"(c[3])
        : "r"(a0), "r"(a1), "r"(a2), "r"(a3), "r"(b0), "r"(b1));
}

// ---------------- tf32 GEMM, cp.async double-buffered ------------------------
// Inputs A and W must already be tf32-rounded fp32 (producers round at write).
// A stage: [128][36] floats; W stage: [32][136] floats.
__global__ __launch_bounds__(256) void tgemm_kernel(
    const float* __restrict__ A, const float* __restrict__ W,
    const float* __restrict__ bias, float* __restrict__ C,
    int M, int N, int K, int lda, int remap)
{
    extern __shared__ float ts[];
    float* Asm = ts;             // 2 stages x 4608
    float* Wsm = ts + 9216;      // 2 stages x 4352
    const int tid = threadIdx.x;
    const int m0 = blockIdx.y * 128, n0 = blockIdx.x * 128;
    const int warp = tid >> 5, lane = tid & 31;
    const int wm = (warp & 1) * 64;
    const int wn = (warp >> 1) * 32;
    const int gid = lane >> 2, tig = lane & 3;

    float acc[4][4][4];
#pragma unroll
    for (int mt = 0; mt < 4; mt++)
#pragma unroll
        for (int nt = 0; nt < 4; nt++)
#pragma unroll
            for (int u = 0; u < 4; u++) acc[mt][nt][u] = 0.f;

    auto load_chunk = [&](int st, int k0) {
        float* Ad = Asm + st * 4608;
        float* Wd = Wsm + st * 4352;
#pragma unroll
        for (int i = 0; i < 4; i++) {
            int f4 = tid + i * 256;
            int m = f4 >> 3, kc = f4 & 7;
            cpasync16(&Ad[m * 36 + kc * 4], &A[(size_t)(m0 + m) * lda + k0 + kc * 4]);
        }
#pragma unroll
        for (int i = 0; i < 4; i++) {
            int f4 = tid + i * 256;
            int k = f4 >> 5, nc = f4 & 31;
            cpasync16(&Wd[k * 136 + nc * 4], &W[(size_t)(k0 + k) * N + n0 + nc * 4]);
        }
    };

    auto compute = [&](int st) {
        const float* As = Asm + st * 4608;
        const float* Ws = Wsm + st * 4352;
#pragma unroll
        for (int kk = 0; kk < 4; kk++) {
            unsigned bf[4][2];
#pragma unroll
            for (int nt = 0; nt < 4; nt++) {
                bf[nt][0] = __float_as_uint(Ws[(kk * 8 + tig) * 136 + wn + nt * 8 + gid]);
                bf[nt][1] = __float_as_uint(Ws[(kk * 8 + 4 + tig) * 136 + wn + nt * 8 + gid]);
            }
#pragma unroll
            for (int mt = 0; mt < 4; mt++) {
                int r0 = (wm + mt * 16 + gid) * 36;
                int r1 = (wm + mt * 16 + 8 + gid) * 36;
                unsigned a0 = __float_as_uint(As[r0 + kk * 8 + tig]);
                unsigned a1 = __float_as_uint(As[r1 + kk * 8 + tig]);
                unsigned a2 = __float_as_uint(As[r0 + kk * 8 + 4 + tig]);
                unsigned a3 = __float_as_uint(As[r1 + kk * 8 + 4 + tig]);
#pragma unroll
                for (int nt = 0; nt < 4; nt++)
                    mma_tf32(acc[mt][nt], a0, a1, a2, a3, bf[nt][0], bf[nt][1]);
            }
        }
    };

    load_chunk(0, 0);
    asm volatile("cp.async.commit_group;\n");
    const int nch = K >> 5;
    for (int ch = 0; ch < nch; ch++) {
        if (ch + 1 < nch) {
            load_chunk((ch + 1) & 1, (ch + 1) * 32);
            asm volatile("cp.async.commit_group;\n");
            asm volatile("cp.async.wait_group 1;\n");
        } else {
            asm volatile("cp.async.wait_group 0;\n");
        }
        __syncthreads();
        compute(ch & 1);
        __syncthreads();
    }

#pragma unroll
    for (int nt = 0; nt < 4; nt++) {
        int col = n0 + wn + nt * 8 + 2 * tig;
        float b0v = bias[col], b1v = bias[col + 1];
#pragma unroll
        for (int mt = 0; mt < 4; mt++) {
            int row0 = m0 + wm + mt * 16 + gid;
            int row1 = row0 + 8;
            int o0 = remap ? ((row0 & (BB - 1)) * TT + (row0 >> 7)) : row0;
            int o1 = remap ? ((row1 & (BB - 1)) * TT + (row1 >> 7)) : row1;
            float2 v0, v1;
            v0.x = acc[mt][nt][0] + b0v; v0.y = acc[mt][nt][1] + b1v;
            v1.x = acc[mt][nt][2] + b0v; v1.y = acc[mt][nt][3] + b1v;
            *reinterpret_cast<float2*>(&C[(size_t)o0 * N + col]) = v0;
            *reinterpret_cast<float2*>(&C[(size_t)o1 * N + col]) = v1;
        }
    }
}

// ---------------- bridge ----------------------------------------------------
__global__ void bridge_kernel(const float* __restrict__ hW, const float* __restrict__ hb,
                              const float* __restrict__ cW, const float* __restrict__ cb)
{
    int p = blockIdx.x * blockDim.x + threadIdx.x;
    int j = p & (HH - 1);
    int b = p >> 9;
    float sh = hb[j], sc = cb[j];
    const float* hrow = g_fin[0] + (size_t)b * 2 * HH;
    const float* crow = g_fin[1] + (size_t)b * 2 * HH;
    for (int k = 0; k < 2 * HH; k++) {
        sh += hrow[k] * hW[(size_t)k * HH + j];
        sc += crow[k] * cW[(size_t)k * HH + j];
    }
    g_hinit[(size_t)b * HH + j] = tanhf(sh);
    g_cinit[(size_t)b * HH + j] = tanhf(sc);
}

// ---------------- bf16 MMA recurrence ----------------------------------------
__device__ __forceinline__ void mma_bf16(float* c, const unsigned* a,
                                         unsigned b0, unsigned b1) {
    asm volatile(
        "mma.sync.aligned.m16n8k16.row.col.f32.bf16.bf16.f32 "
        "{%0,%1,%2,%3}, {%4,%5,%6,%7}, {%8,%9}, {%0,%1,%2,%3};"
        : "+f"(c[0]), "+f"(c[1]), "+f"(c[2]), "+f"(c[3])
        : "r"(a[0]), "r"(a[1]), "r"(a[2]), "r"(a[3]), "r"(b0), "r"(b1));
}

__device__ __forceinline__ float sigm_(float v) { return 1.f / (1.f + expf(-v)); }

struct RCell2 {
    const float* pre;
    const unsigned* whi; const unsigned* wlo;
    float* hs; int ldh; int colofs;
    const float* cinit;
    unsigned* h0hi; unsigned* h0lo;
    unsigned* h1hi; unsigned* h1lo;
    float* finH; float* finC; int finOfs;
    int rev;
};

template <int MT>
__global__ __launch_bounds__(256) void recur2_kernel(
    RCell2 c0, RCell2 c1, int nbpc, unsigned nb, unsigned* barC)
{
    extern __shared__ unsigned smu[];
    unsigned* Wphi = smu;             // 256*72
    unsigned* Wplo = smu + 18432;
    unsigned* Aphi = smu + 36864;     // 64*72
    unsigned* Aplo = smu + 41472;
    float* ex = (float*)(smu + 46080);  // 64*72 floats

    const int tid = threadIdx.x;
    const bool c1sel = (blockIdx.x >= nbpc);
    const RCell2 C = c1sel ? c1 : c0;
    const int bic = c1sel ? (blockIdx.x - nbpc) : blockIdx.x;
    const int bn = bic & 31;
    const int m0 = (bic >> 5) * MT;
    const int j0 = bn * 16;
    const int warp = tid >> 5, lane = tid & 31;
    const int gid = lane >> 2, tig = lane & 3;
    const int wm = warp & 1, wn = warp >> 1;
    constexpr int WTM = MT / 32;

    {
        const uint4* srch = reinterpret_cast<const uint4*>(C.whi + (size_t)bn * 16384);
        const uint4* srcl = reinterpret_cast<const uint4*>(C.wlo + (size_t)bn * 16384);
#pragma unroll
        for (int i = 0; i < 16; i++) {
            int f4 = tid + i * 256;
            int row = f4 >> 4, q = f4 & 15;
            *reinterpret_cast<uint4*>(&Wphi[row * 72 + q * 4]) = srch[f4];
            *reinterpret_cast<uint4*>(&Wplo[row * 72 + q * 4]) = srcl[f4];
        }
    }

    const int pm = tid & (MT - 1);
    const int pjq = tid / MT;
    const bool pact = pjq < 4;
    float creg[4] = {0.f, 0.f, 0.f, 0.f};
    if (pact && C.cinit) {
        float4 cv = __ldcg(reinterpret_cast<const float4*>(
            &C.cinit[(size_t)(m0 + pm) * HH + j0 + pjq * 4]));
        creg[0] = cv.x; creg[1] = cv.y; creg[2] = cv.z; creg[3] = cv.w;
    }
    __syncthreads();

    for (int s = 0; s < TT; s++) {
        const int t = C.rev ? (TT - 1 - s) : s;
        const unsigned* rhi = (s & 1) ? C.h1hi : C.h0hi;
        const unsigned* rlo = (s & 1) ? C.h1lo : C.h0lo;
        unsigned* whi_ = (s & 1) ? C.h0hi : C.h1hi;
        unsigned* wlo_ = (s & 1) ? C.h0lo : C.h1lo;
        const float* preb = C.pre + (size_t)t * BB * G4;

        float4 pg[4];
        if (pact) {
#pragma unroll
            for (int g = 0; g < 4; g++)
                pg[g] = __ldg(reinterpret_cast<const float4*>(
                    &preb[(size_t)(m0 + pm) * G4 + g * HH + j0 + pjq * 4]));
        }

        float acc[WTM][2][4];
#pragma unroll
        for (int mt = 0; mt < WTM; mt++)
#pragma unroll
            for (int nt = 0; nt < 2; nt++)
#pragma unroll
                for (int u = 0; u < 4; u++) acc[mt][nt][u] = 0.f;

        for (int ch = 0; ch < 4; ch++) {
            __syncthreads();
            {
                constexpr int F4 = 64 * MT / 4;
                constexpr int PT = F4 / 256;
                const int kpb = ch * 64;
#pragma unroll
                for (int i = 0; i < PT; i++) {
                    int f4 = tid + i * 256;
                    int row = f4 / (MT / 4), q = f4 % (MT / 4);
                    *reinterpret_cast<uint4*>(&Aphi[row * 72 + q * 4]) =
                        __ldcg(reinterpret_cast<const uint4*>(
                            &rhi[(size_t)(kpb + row) * 128 + m0 + q * 4]));
                    *reinterpret_cast<uint4*>(&Aplo[row * 72 + q * 4]) =
                        __ldcg(reinterpret_cast<const uint4*>(
                            &rlo[(size_t)(kpb + row) * 128 + m0 + q * 4]));
                }
            }
            __syncthreads();
#pragma unroll
            for (int kc = 0; kc < 8; kc++) {
                const int r0 = (kc * 8 + tig) * 72;
                const int r1 = r0 + 4 * 72;
                unsigned ah[WTM][4], al[WTM][4];
#pragma unroll
                for (int mt = 0; mt < WTM; mt++) {
                    const int am = wm * (MT / 2) + mt * 16 + gid;
                    ah[mt][0] = Aphi[r0 + am]; ah[mt][1] = Aphi[r0 + am + 8];
                    ah[mt][2] = Aphi[r1 + am]; ah[mt][3] = Aphi[r1 + am + 8];
                    al[mt][0] = Aplo[r0 + am]; al[mt][1] = Aplo[r0 + am + 8];
                    al[mt][2] = Aplo[r1 + am]; al[mt][3] = Aplo[r1 + am + 8];
                }
                const int wr0 = (ch * 64 + kc * 8 + tig) * 72;
                const int wr1 = wr0 + 4 * 72;
#pragma unroll
                for (int nt = 0; nt < 2; nt++) {
                    const int nn = wn * 16 + nt * 8 + gid;
                    unsigned bh0 = Wphi[wr0 + nn], bh1 = Wphi[wr1 + nn];
                    unsigned bl0 = Wplo[wr0 + nn], bl1 = Wplo[wr1 + nn];
#pragma unroll
                    for (int mt = 0; mt < WTM; mt++) {
                        mma_bf16(acc[mt][nt], ah[mt], bh0, bh1);
                        mma_bf16(acc[mt][nt], ah[mt], bl0, bl1);
                        mma_bf16(acc[mt][nt], al[mt], bh0, bh1);
                    }
                }
            }
        }

#pragma unroll
        for (int mt = 0; mt < WTM; mt++)
#pragma unroll
            for (int nt = 0; nt < 2; nt++) {
                int mr = (wm * (MT / 2) + mt * 16 + gid) * 72;
                int col = wn * 16 + nt * 8 + 2 * tig;
                float2 v0, v1;
                v0.x = acc[mt][nt][0]; v0.y = acc[mt][nt][1];
                v1.x = acc[mt][nt][2]; v1.y = acc[mt][nt][3];
                *reinterpret_cast<float2*>(&ex[mr + col]) = v0;
                *reinterpret_cast<float2*>(&ex[mr + 8 * 72 + col]) = v1;
            }
        __syncthreads();

        if (pact) {
            float4 gi = *reinterpret_cast<const float4*>(&ex[pm * 72 + 0  + pjq * 4]);
            float4 gf = *reinterpret_cast<const float4*>(&ex[pm * 72 + 16 + pjq * 4]);
            float4 gg = *reinterpret_cast<const float4*>(&ex[pm * 72 + 32 + pjq * 4]);
            float4 go = *reinterpret_cast<const float4*>(&ex[pm * 72 + 48 + pjq * 4]);
            float I[4] = {gi.x + pg[0].x, gi.y + pg[0].y, gi.z + pg[0].z, gi.w + pg[0].w};
            float F[4] = {gf.x + pg[1].x, gf.y + pg[1].y, gf.z + pg[1].z, gf.w + pg[1].w};
            float Gg[4] = {gg.x + pg[2].x, gg.y + pg[2].y, gg.z + pg[2].z, gg.w + pg[2].w};
            float O[4] = {go.x + pg[3].x, go.y + pg[3].y, go.z + pg[3].z, go.w + pg[3].w};
            float hn[4];
#pragma unroll
            for (int u = 0; u < 4; u++) {
                float cn = sigm_(F[u]) * creg[u] + sigm_(I[u]) * tanhf(Gg[u]);
                hn[u] = sigm_(O[u]) * tanhf(cn);
                creg[u] = cn;
            }
            __nv_bfloat16 b0 = __float2bfloat16_rn(hn[0]);
            __nv_bfloat16 b1 = __float2bfloat16_rn(hn[1]);
            __nv_bfloat16 b2 = __float2bfloat16_rn(hn[2]);
            __nv_bfloat16 b3 = __float2bfloat16_rn(hn[3]);
            unsigned hp0 = (unsigned)__bfloat16_as_ushort(b0) |
                           ((unsigned)__bfloat16_as_ushort(b1) << 16);
            unsigned hp1 = (unsigned)__bfloat16_as_ushort(b2) |
                           ((unsigned)__bfloat16_as_ushort(b3) << 16);
            unsigned lp0 = pack_bf16x2(hn[0] - __bfloat162float(b0),
                                       hn[1] - __bfloat162float(b1));
            unsigned lp1 = pack_bf16x2(hn[2] - __bfloat162float(b2),
                                       hn[3] - __bfloat162float(b3));
            int kp0 = (j0 + pjq * 4) >> 1;
            __stcg(&whi_[(size_t)kp0 * 128 + m0 + pm], hp0);
            __stcg(&whi_[(size_t)(kp0 + 1) * 128 + m0 + pm], hp1);
            __stcg(&wlo_[(size_t)kp0 * 128 + m0 + pm], lp0);
            __stcg(&wlo_[(size_t)(kp0 + 1) * 128 + m0 + pm], lp1);
            if (C.hs) {
                // tf32-round at write: the only consumer is the tf32 pre-GEMM
                float4 hv;
                hv.x = tfr(hn[0]); hv.y = tfr(hn[1]);
                hv.z = tfr(hn[2]); hv.w = tfr(hn[3]);
                *reinterpret_cast<float4*>(
                    &C.hs[(size_t)t * BB * C.ldh + (size_t)(m0 + pm) * C.ldh +
                          C.colofs + j0 + pjq * 4]) = hv;
            }
            if (s == TT - 1 && C.finH) {
                float4 hv; hv.x = hn[0]; hv.y = hn[1]; hv.z = hn[2]; hv.w = hn[3];
                float4 cv; cv.x = creg[0]; cv.y = creg[1]; cv.z = creg[2]; cv.w = creg[3];
                *reinterpret_cast<float4*>(
                    &C.finH[(size_t)(m0 + pm) * 2 * HH + C.finOfs + j0 + pjq * 4]) = hv;
                *reinterpret_cast<float4*>(
                    &C.finC[(size_t)(m0 + pm) * 2 * HH + C.finOfs + j0 + pjq * 4]) = cv;
            }
        }

        __threadfence();
        __syncthreads();
        if (tid == 0) {
            atomicAdd(barC, 1u);
            unsigned target = (unsigned)(s + 1) * nb;
            while (*((volatile unsigned*)barC) < target) __nanosleep(64);
            __threadfence();
        }
        __syncthreads();
    }
}

// ---------------- host ------------------------------------------------------
static void* symaddr_(const void* sym) {
    void* p = nullptr;
    cudaGetSymbolAddress(&p, sym);
    return p;
}

extern "C" void kernel_launch(void* const* d_in, const int* in_sizes, int n_in,
                              void* d_out, int out_size)
{
    const int*   x       = (const int*)  d_in[0];
    const float* emb     = (const float*)d_in[1];
    const float* efWx0   = (const float*)d_in[2];
    const float* efWh0   = (const float*)d_in[3];
    const float* efb0    = (const float*)d_in[4];
    const float* efWx1   = (const float*)d_in[5];
    const float* efWh1   = (const float*)d_in[6];
    const float* efb1    = (const float*)d_in[7];
    const float* ebWx0   = (const float*)d_in[8];
    const float* ebWh0   = (const float*)d_in[9];
    const float* ebb0    = (const float*)d_in[10];
    const float* ebWx1   = (const float*)d_in[11];
    const float* ebWh1   = (const float*)d_in[12];
    const float* ebb1    = (const float*)d_in[13];
    const float* dWx0    = (const float*)d_in[14];
    const float* dWh0    = (const float*)d_in[15];
    const float* db0     = (const float*)d_in[16];
    const float* dWx1    = (const float*)d_in[17];
    const float* dWh1    = (const float*)d_in[18];
    const float* db1     = (const float*)d_in[19];
    const float* hprojW  = (const float*)d_in[20];
    const float* hprojb  = (const float*)d_in[21];
    const float* cprojW  = (const float*)d_in[22];
    const float* cprojb  = (const float*)d_in[23];
    const float* fcW     = (const float*)d_in[24];
    const float* fcb     = (const float*)d_in[25];

    float* pX    = (float*)symaddr_(g_X);
    float* pPre0 = (float*)symaddr_(g_pre0);
    float* pPre1 = (float*)symaddr_(g_pre1);
    float* pCat  = (float*)symaddr_(g_cat);
    float* pHs0  = (float*)symaddr_(g_hs0);
    float* pHs1  = (float*)symaddr_(g_hs1);
    float* pFin  = (float*)symaddr_(g_fin);
    float* pHin  = (float*)symaddr_(g_hinit);
    float* pCin  = (float*)symaddr_(g_cinit);
    unsigned* pBar = (unsigned*)symaddr_(g_barC);
    unsigned* pWsp = (unsigned*)symaddr_(g_wsp);
    unsigned* pHsp = (unsigned*)symaddr_(g_hsp);
    float* pWx   = (float*)symaddr_(g_wx);

    const int M = TT * BB;
    const int SME2 = 50688 * 4;      // recurrence smem
    const int SMEG = 17920 * 4;      // tgemm smem (71680 B)
    cudaFuncSetAttribute(recur2_kernel<64>, cudaFuncAttributeMaxDynamicSharedMemorySize, SME2);
    cudaFuncSetAttribute(recur2_kernel<32>, cudaFuncAttributeMaxDynamicSharedMemorySize, SME2);
    cudaFuncSetAttribute(tgemm_kernel, cudaFuncAttributeMaxDynamicSharedMemorySize, SMEG);

    const size_t WSZ = 32 * 256 * 64;
    auto wsp = [&](int w, int hl) { return pWsp + ((size_t)w * 2 + hl) * WSZ; };
    auto hsp = [&](int cell, int buf, int hl) {
        return pHsp + (((size_t)cell * 2 + buf) * 2 + hl) * 32768;
    };
    auto wx = [&](int i) { return pWx + (size_t)i * 2097152; };

    // 0a. split recurrent weights to bf16 hi/lo
    wconv_kernel<<<2048, 256>>>(efWh0, wsp(0, 0), wsp(0, 1));
    wconv_kernel<<<2048, 256>>>(ebWh0, wsp(1, 0), wsp(1, 1));
    wconv_kernel<<<2048, 256>>>(efWh1, wsp(2, 0), wsp(2, 1));
    wconv_kernel<<<2048, 256>>>(ebWh1, wsp(3, 0), wsp(3, 1));
    wconv_kernel<<<2048, 256>>>(dWh0,  wsp(4, 0), wsp(4, 1));
    wconv_kernel<<<2048, 256>>>(dWh1,  wsp(5, 0), wsp(5, 1));

    // 0b. tf32-round input weights
    tfround_kernel<<<2048, 256>>>(efWx0, wx(0), EE * G4);
    tfround_kernel<<<2048, 256>>>(ebWx0, wx(1), EE * G4);
    tfround_kernel<<<8192, 256>>>(efWx1, wx(2), 2 * HH * G4);
    tfround_kernel<<<8192, 256>>>(ebWx1, wx(3), 2 * HH * G4);
    tfround_kernel<<<2048, 256>>>(dWx0,  wx(4), EE * G4);
    tfround_kernel<<<4096, 256>>>(dWx1,  wx(5), HH * G4);
    tfround_kernel<<<1024, 256>>>(fcW,   wx(6), HH * VV);

    // 1. embedding (tf32-rounded at write)
    embed_kernel<<<TT * BB * (EE / 4) / 256, 256>>>(x, emb);

    // 2. enc L0 precompute (K=256)
    dim3 gpre(G4 / 128, M / 128);
    tgemm_kernel<<<gpre, 256, SMEG>>>(pX, wx(0), efb0, pPre0, M, G4, EE, EE, 0);
    tgemm_kernel<<<gpre, 256, SMEG>>>(pX, wx(1), ebb0, pPre1, M, G4, EE, EE, 0);

    // 3. enc L0 recurrence
    initbar_kernel<<<1, 1>>>(pBar);
    zero_kernel<<<1024, 256>>>((float*)pHsp, 262144);
    {
        RCell2 cf{pPre0, wsp(0, 0), wsp(0, 1), pCat, 2 * HH, 0, nullptr,
                  hsp(0, 0, 0), hsp(0, 0, 1), hsp(0, 1, 0), hsp(0, 1, 1),
                  nullptr, nullptr, 0, 0};
        RCell2 cb{pPre1, wsp(1, 0), wsp(1, 1), pCat, 2 * HH, HH, nullptr,
                  hsp(1, 0, 0), hsp(1, 0, 1), hsp(1, 1, 0), hsp(1, 1, 1),
                  nullptr, nullptr, 0, 1};
        recur2_kernel<64><<<128, 256, SME2>>>(cf, cb, 64, 128u, pBar);
    }

    // 4. enc L1 precompute (K=1024)
    tgemm_kernel<<<gpre, 256, SMEG>>>(pCat, wx(2), efb1, pPre0, M, G4, 2 * HH, 2 * HH, 0);
    tgemm_kernel<<<gpre, 256, SMEG>>>(pCat, wx(3), ebb1, pPre1, M, G4, 2 * HH, 2 * HH, 0);

    // 5. enc L1 recurrence (finals only)
    initbar_kernel<<<1, 1>>>(pBar);
    zero_kernel<<<1024, 256>>>((float*)pHsp, 262144);
    {
        RCell2 ef{pPre0, wsp(2, 0), wsp(2, 1), nullptr, 0, 0, nullptr,
                  hsp(0, 0, 0), hsp(0, 0, 1), hsp(0, 1, 0), hsp(0, 1, 1),
                  pFin, pFin + (size_t)BB * 2 * HH, 0, 0};
        RCell2 eb{pPre1, wsp(3, 0), wsp(3, 1), nullptr, 0, 0, nullptr,
                  hsp(1, 0, 0), hsp(1, 0, 1), hsp(1, 1, 0), hsp(1, 1, 1),
                  pFin, pFin + (size_t)BB * 2 * HH, HH, 1};
        recur2_kernel<64><<<128, 256, SME2>>>(ef, eb, 64, 128u, pBar);
    }

    // 6. bridge
    bridge_kernel<<<(BB * HH) / 256, 256>>>(hprojW, hprojb, cprojW, cprojb);

    // 7. dec L0 (K=256)
    tgemm_kernel<<<gpre, 256, SMEG>>>(pX, wx(4), db0, pPre0, M, G4, EE, EE, 0);
    initbar_kernel<<<1, 1>>>(pBar);
    hsplit_kernel<<<128, 256>>>(pHin, hsp(0, 0, 0), hsp(0, 0, 1));
    {
        RCell2 d0{pPre0, wsp(4, 0), wsp(4, 1), pHs0, HH, 0, pCin,
                  hsp(0, 0, 0), hsp(0, 0, 1), hsp(0, 1, 0), hsp(0, 1, 1),
                  nullptr, nullptr, 0, 0};
        recur2_kernel<32><<<128, 256, SME2>>>(d0, d0, 128, 128u, pBar);
    }

    // 8. dec L1 (K=512)
    tgemm_kernel<<<gpre, 256, SMEG>>>(pHs0, wx(5), db1, pPre1, M, G4, HH, HH, 0);
    initbar_kernel<<<1, 1>>>(pBar);
    hsplit_kernel<<<128, 256>>>(pHin, hsp(0, 0, 0), hsp(0, 0, 1));
    {
        RCell2 d1{pPre1, wsp(5, 0), wsp(5, 1), pHs1, HH, 0, pCin,
                  hsp(0, 0, 0), hsp(0, 0, 1), hsp(0, 1, 0), hsp(0, 1, 1),
                  nullptr, nullptr, 0, 0};
        recur2_kernel<32><<<128, 256, SME2>>>(d1, d1, 128, 128u, pBar);
    }

    // 9. final FC with remap
    dim3 gfc(VV / 128, M / 128);
    tgemm_kernel<<<gfc, 256, SMEG>>>(pHs1, wx(6), fcb, (float*)d_out, M, VV, HH, HH, 1);
}